// round 1
// baseline (speedup 1.0000x reference)
#include <cuda_runtime.h>
#include <cuda_bf16.h>

// Problem constants (fixed by the dataset)
#define NN 50000
#define EE 800000
#define DD 128
#define HH 64
#define GG 512

// ---------------- device scratch (static allocation only) ----------------
__device__ float g_h[(size_t)NN * DD];     // GEMM output of current layer
__device__ float g_agg[(size_t)NN * DD];   // aggregated (relu'd) layer output
__device__ float g_dinv[NN];
__device__ int   g_deg[NN];                // indegree + 1 (self loop)
__device__ int   g_fill[NN];
__device__ int   g_rowptr[NN + 1];
__device__ int   g_csrc[EE];
__device__ float g_cnorm[EE];
__device__ int   g_gcnt[GG];
__device__ int   g_gptr[GG + 1];

// ---------------- prep kernels ----------------
__global__ void k_init_nodes() {
    int i = blockIdx.x * blockDim.x + threadIdx.x;
    if (i < NN) { g_deg[i] = 1; g_fill[i] = 0; }
}

__global__ void k_init_graphs() {
    int i = blockIdx.x * blockDim.x + threadIdx.x;
    if (i < GG) g_gcnt[i] = 0;
}

__global__ void k_hist(const int* __restrict__ dst) {
    int e = blockIdx.x * blockDim.x + threadIdx.x;
    if (e < EE) atomicAdd(&g_deg[dst[e]], 1);
}

__global__ void k_bhist(const int* __restrict__ batch) {
    int i = blockIdx.x * blockDim.x + threadIdx.x;
    if (i < NN) atomicAdd(&g_gcnt[batch[i]], 1);
}

__global__ void k_dinv() {
    int i = blockIdx.x * blockDim.x + threadIdx.x;
    if (i < NN) g_dinv[i] = rsqrtf((float)g_deg[i]);  // deg >= 1 always
}

// single-block exclusive scan: out[0]=0, out[i+1]=sum_{j<=i}(in[j]-sub)
__device__ void scan_ex_dev(const int* in, int* out, int n, int sub) {
    __shared__ int wsum[32];
    __shared__ int s_carry;
    int tid = threadIdx.x, lane = tid & 31, wid = tid >> 5;
    if (tid == 0) { s_carry = 0; out[0] = 0; }
    __syncthreads();
    for (int base = 0; base < n; base += 1024) {
        int i = base + tid;
        int v = (i < n) ? (in[i] - sub) : 0;
        int x = v;
        #pragma unroll
        for (int off = 1; off < 32; off <<= 1) {
            int y = __shfl_up_sync(0xffffffff, x, off);
            if (lane >= off) x += y;
        }
        if (lane == 31) wsum[wid] = x;
        __syncthreads();
        if (wid == 0) {
            int w = wsum[lane];
            #pragma unroll
            for (int off = 1; off < 32; off <<= 1) {
                int y = __shfl_up_sync(0xffffffff, w, off);
                if (lane >= off) w += y;
            }
            wsum[lane] = w;
        }
        __syncthreads();
        int offset = (wid > 0 ? wsum[wid - 1] : 0) + s_carry;
        if (i < n) out[i + 1] = x + offset;
        __syncthreads();
        if (tid == 0) s_carry += wsum[31];
        __syncthreads();
    }
}

__global__ void k_scan_rows()   { scan_ex_dev(g_deg,  g_rowptr, NN, 1); }
__global__ void k_scan_graphs() { scan_ex_dev(g_gcnt, g_gptr,   GG, 0); }

__global__ void k_fill(const int* __restrict__ src, const int* __restrict__ dst) {
    int e = blockIdx.x * blockDim.x + threadIdx.x;
    if (e >= EE) return;
    int s = src[e], d = dst[e];
    int p = g_rowptr[d] + atomicAdd(&g_fill[d], 1);
    g_csrc[p] = s;
    g_cnorm[p] = g_dinv[s] * g_dinv[d];
}

// ---------------- GEMM: C[N,128] = A[N,128] @ W[128,128] ----------------
// 128x128 tile per block, 256 threads, 8x8 register blocking, K chunks of 16.
// A_ext == nullptr -> read g_agg. Output always g_h.
__global__ void __launch_bounds__(256) k_gemm(const float* __restrict__ A_ext,
                                              const float* __restrict__ W) {
    const float* A = A_ext ? A_ext : g_agg;
    __shared__ float As[16 * 132];  // As[k][r], padded
    __shared__ float Ws[16 * 128];  // Ws[k][c]

    int tid = threadIdx.x;
    int row0 = blockIdx.x * 128;
    int tr = tid >> 4;   // 0..15 -> rows tr*8..tr*8+7
    int tc = tid & 15;   // 0..15 -> cols tc*8..tc*8+7

    float acc[8][8];
    #pragma unroll
    for (int i = 0; i < 8; i++)
        #pragma unroll
        for (int j = 0; j < 8; j++) acc[i][j] = 0.f;

    for (int kc = 0; kc < 8; kc++) {
        // load A chunk: 128 rows x 16 k, transposed into As[k][r]
        #pragma unroll
        for (int i = 0; i < 2; i++) {
            int id = tid + i * 256;
            int r = id >> 2;          // 0..127
            int kq = id & 3;          // quad within chunk
            int grow = row0 + r;
            float4 v = make_float4(0.f, 0.f, 0.f, 0.f);
            if (grow < NN)
                v = *(const float4*)&A[(size_t)grow * DD + kc * 16 + kq * 4];
            As[(kq * 4 + 0) * 132 + r] = v.x;
            As[(kq * 4 + 1) * 132 + r] = v.y;
            As[(kq * 4 + 2) * 132 + r] = v.z;
            As[(kq * 4 + 3) * 132 + r] = v.w;
        }
        // load W chunk: 16 k-rows x 128 cols
        #pragma unroll
        for (int i = 0; i < 2; i++) {
            int id = tid + i * 256;
            int kr = id >> 5;         // 0..15
            int cq = id & 31;         // 0..31
            *(float4*)&Ws[kr * 128 + cq * 4] =
                *(const float4*)&W[(kc * 16 + kr) * DD + cq * 4];
        }
        __syncthreads();

        #pragma unroll
        for (int k = 0; k < 16; k++) {
            float a[8], b[8];
            *(float4*)&a[0] = *(const float4*)&As[k * 132 + tr * 8];
            *(float4*)&a[4] = *(const float4*)&As[k * 132 + tr * 8 + 4];
            *(float4*)&b[0] = *(const float4*)&Ws[k * 128 + tc * 8];
            *(float4*)&b[4] = *(const float4*)&Ws[k * 128 + tc * 8 + 4];
            #pragma unroll
            for (int i = 0; i < 8; i++)
                #pragma unroll
                for (int j = 0; j < 8; j++)
                    acc[i][j] = fmaf(a[i], b[j], acc[i][j]);
        }
        __syncthreads();
    }

    #pragma unroll
    for (int i = 0; i < 8; i++) {
        int grow = row0 + tr * 8 + i;
        if (grow < NN) {
            *(float4*)&g_h[(size_t)grow * DD + tc * 8]     = *(float4*)&acc[i][0];
            *(float4*)&g_h[(size_t)grow * DD + tc * 8 + 4] = *(float4*)&acc[i][4];
        }
    }
}

// ---------------- aggregation: out[i] = relu(sum_{e->i} h[src]*norm + h[i]*dinv^2 + b)
__global__ void __launch_bounds__(256) k_aggregate(const float* __restrict__ bias) {
    int node = blockIdx.x * 8 + (threadIdx.x >> 5);
    if (node >= NN) return;
    int lane = threadIdx.x & 31;
    const float4* h4 = (const float4*)g_h;

    float di = g_dinv[node];
    float w0 = di * di;
    float4 acc = h4[node * 32 + lane];
    float4 bb = ((const float4*)bias)[lane];
    acc.x = fmaf(acc.x, w0, bb.x);
    acc.y = fmaf(acc.y, w0, bb.y);
    acc.z = fmaf(acc.z, w0, bb.z);
    acc.w = fmaf(acc.w, w0, bb.w);

    int s = g_rowptr[node], e = g_rowptr[node + 1];
    #pragma unroll 4
    for (int j = s; j < e; j++) {
        int u = g_csrc[j];
        float w = g_cnorm[j];
        float4 v = h4[u * 32 + lane];
        acc.x = fmaf(v.x, w, acc.x);
        acc.y = fmaf(v.y, w, acc.y);
        acc.z = fmaf(v.z, w, acc.z);
        acc.w = fmaf(v.w, w, acc.w);
    }
    acc.x = fmaxf(acc.x, 0.f);
    acc.y = fmaxf(acc.y, 0.f);
    acc.z = fmaxf(acc.z, 0.f);
    acc.w = fmaxf(acc.w, 0.f);
    ((float4*)g_agg)[node * 32 + lane] = acc;
}

// ---------------- pool (mean per graph) + classifier ----------------
__global__ void __launch_bounds__(128) k_pool_cls(const float* __restrict__ Wc,
                                                  const float* __restrict__ bc,
                                                  const float* __restrict__ Wo,
                                                  const float* __restrict__ bo,
                                                  float* __restrict__ out) {
    __shared__ float pooled[DD];
    __shared__ float zs[HH];
    int g = blockIdx.x, c = threadIdx.x;
    int s = g_gptr[g], e = g_gptr[g + 1];
    float acc = 0.f;
    for (int i = s; i < e; i++) acc += g_agg[(size_t)i * DD + c];
    pooled[c] = acc / fmaxf((float)(e - s), 1.0f);
    __syncthreads();
    if (c < HH) {
        float z = bc[c];
        #pragma unroll
        for (int d = 0; d < DD; d++) z = fmaf(pooled[d], Wc[d * HH + c], z);
        z = fmaxf(z, 0.f);
        zs[c] = z * Wo[c];
    }
    __syncthreads();
    if (c == 0) {
        float r = bo[0];
        #pragma unroll
        for (int h = 0; h < HH; h++) r += zs[h];
        out[g] = r;
    }
}

// ---------------- launch ----------------
extern "C" void kernel_launch(void* const* d_in, const int* in_sizes, int n_in,
                              void* d_out, int out_size) {
    const float* x  = (const float*)d_in[0];
    const int*   ei = (const int*)d_in[1];      // [2, E] int32
    const int*   batch = (const int*)d_in[2];
    const float* W1 = (const float*)d_in[3];
    const float* b1 = (const float*)d_in[4];
    const float* W2 = (const float*)d_in[5];
    const float* b2 = (const float*)d_in[6];
    const float* W3 = (const float*)d_in[7];
    const float* b3 = (const float*)d_in[8];
    const float* Wc = (const float*)d_in[9];
    const float* bc = (const float*)d_in[10];
    const float* Wo = (const float*)d_in[11];
    const float* bo = (const float*)d_in[12];
    float* out = (float*)d_out;

    const int* src = ei;
    const int* dst = ei + EE;

    const int NB_N = (NN + 255) / 256;
    const int NB_E = (EE + 255) / 256;

    // graph structure (once per call)
    k_init_nodes<<<NB_N, 256>>>();
    k_init_graphs<<<(GG + 255) / 256, 256>>>();
    k_hist<<<NB_E, 256>>>(dst);
    k_bhist<<<NB_N, 256>>>(batch);
    k_dinv<<<NB_N, 256>>>();
    k_scan_rows<<<1, 1024>>>();
    k_scan_graphs<<<1, 1024>>>();
    k_fill<<<NB_E, 256>>>(src, dst);

    const int NB_G = (NN + 127) / 128;    // gemm blocks
    const int NB_A = (NN + 7) / 8;        // aggregate blocks

    // layer 1 (reads x)
    k_gemm<<<NB_G, 256>>>(x, W1);
    k_aggregate<<<NB_A, 256>>>(b1);
    // layer 2
    k_gemm<<<NB_G, 256>>>(nullptr, W2);
    k_aggregate<<<NB_A, 256>>>(b2);
    // layer 3
    k_gemm<<<NB_G, 256>>>(nullptr, W3);
    k_aggregate<<<NB_A, 256>>>(b3);

    // pool + classifier
    k_pool_cls<<<GG, 128>>>(Wc, bc, Wo, bo, out);
}

// round 3
// speedup vs baseline: 1.1191x; 1.1191x over previous
#include <cuda_runtime.h>
#include <cuda_bf16.h>
#include <cuda_fp16.h>
#include <cstdint>

// Problem constants (fixed by the dataset)
#define NN 50000
#define EE 800000
#define DD 128
#define HH 64
#define GG 512

// ---------------- device scratch (static allocation only) ----------------
__device__ __half g_h[(size_t)NN * DD];    // GEMM output of current layer (fp16)
__device__ float  g_agg[(size_t)NN * DD];  // aggregated (relu'd) layer output, fp32
__device__ float  g_dinv[NN];
__device__ int    g_deg[NN];               // indegree + 1 (self loop)
__device__ int    g_fill[NN];
__device__ int    g_rowptr[NN + 1];
__device__ int    g_csrc[EE];
__device__ float  g_cnorm[EE];
__device__ int    g_gptr[GG + 1];

__device__ __forceinline__ uint32_t smem_u32(const void* p) {
    uint32_t a;
    asm("{ .reg .u64 t; cvta.to.shared.u64 t, %1; cvt.u32.u64 %0, t; }"
        : "=r"(a) : "l"(p));
    return a;
}

// ---------------- prep kernels ----------------
__global__ void k_init_nodes() {
    int i = blockIdx.x * blockDim.x + threadIdx.x;
    if (i < NN) { g_deg[i] = 1; g_fill[i] = 0; }
}

__global__ void k_hist(const int* __restrict__ dst) {
    int e = blockIdx.x * blockDim.x + threadIdx.x;
    if (e < EE) atomicAdd(&g_deg[dst[e]], 1);
}

__global__ void k_dinv() {
    int i = blockIdx.x * blockDim.x + threadIdx.x;
    if (i < NN) g_dinv[i] = rsqrtf((float)g_deg[i]);  // deg >= 1 always
}

// batch is sorted: gptr[g] = lower_bound(batch, g)
__global__ void k_gptr(const int* __restrict__ batch) {
    int g = threadIdx.x;  // 512 threads, 1 block
    int lo = 0, hi = NN;
    while (lo < hi) {
        int m = (lo + hi) >> 1;
        if (batch[m] < g) lo = m + 1; else hi = m;
    }
    g_gptr[g] = lo;
    if (g == 0) g_gptr[GG] = NN;
}

// single-block exclusive scan of (deg-1): rowptr over incoming edges
__global__ void k_scan_rows() {
    __shared__ int wsum[32];
    __shared__ int s_carry;
    int tid = threadIdx.x, lane = tid & 31, wid = tid >> 5;
    if (tid == 0) { s_carry = 0; g_rowptr[0] = 0; }
    __syncthreads();
    for (int base = 0; base < NN; base += 1024) {
        int i = base + tid;
        int x = (i < NN) ? (g_deg[i] - 1) : 0;
        #pragma unroll
        for (int off = 1; off < 32; off <<= 1) {
            int y = __shfl_up_sync(0xffffffff, x, off);
            if (lane >= off) x += y;
        }
        if (lane == 31) wsum[wid] = x;
        __syncthreads();
        if (wid == 0) {
            int w = wsum[lane];
            #pragma unroll
            for (int off = 1; off < 32; off <<= 1) {
                int y = __shfl_up_sync(0xffffffff, w, off);
                if (lane >= off) w += y;
            }
            wsum[lane] = w;
        }
        __syncthreads();
        int offset = (wid > 0 ? wsum[wid - 1] : 0) + s_carry;
        if (i < NN) g_rowptr[i + 1] = x + offset;
        __syncthreads();
        if (tid == 0) s_carry += wsum[31];
        __syncthreads();
    }
}

__global__ void k_fill(const int* __restrict__ src, const int* __restrict__ dst) {
    int e = blockIdx.x * blockDim.x + threadIdx.x;
    if (e >= EE) return;
    int s = src[e], d = dst[e];
    int p = g_rowptr[d] + atomicAdd(&g_fill[d], 1);
    g_csrc[p] = s;
    g_cnorm[p] = g_dinv[s] * g_dinv[d];
}

// ---------------- HMMA GEMM: g_h[N,128](fp16) = A[N,128](fp32) @ W[128,128] ---
// bf16 hi/lo split, 3 mma products, fp32 accum. 256 thr = 8 warps (2x4), each
// warp computes a 64x32 tile via m16n8k16 mma.sync + ldmatrix.
#define ASTR 136                       // bf16 row stride (17*8; conflict-free ldmatrix)
#define AH_OFF 0
#define AL_OFF (128 * ASTR)
#define BH_OFF (2 * 128 * ASTR)
#define BL_OFF (3 * 128 * ASTR)
#define GSMEM_BYTES (4 * 128 * ASTR * 2)   // 139264

__device__ __forceinline__ void ldsm_x4(uint32_t& r0, uint32_t& r1,
                                        uint32_t& r2, uint32_t& r3, uint32_t a) {
    asm volatile("ldmatrix.sync.aligned.m8n8.x4.shared.b16 {%0,%1,%2,%3}, [%4];"
                 : "=r"(r0), "=r"(r1), "=r"(r2), "=r"(r3) : "r"(a));
}

__device__ __forceinline__ void mma_bf16(float* d, const uint32_t* a,
                                         const uint32_t* b) {
    asm volatile(
        "mma.sync.aligned.m16n8k16.row.col.f32.bf16.bf16.f32 "
        "{%0,%1,%2,%3}, {%4,%5,%6,%7}, {%8,%9}, {%0,%1,%2,%3};"
        : "+f"(d[0]), "+f"(d[1]), "+f"(d[2]), "+f"(d[3])
        : "r"(a[0]), "r"(a[1]), "r"(a[2]), "r"(a[3]), "r"(b[0]), "r"(b[1]));
}

__device__ __forceinline__ uint2 split_pack(float4 v) {
    // hi = rn(bf16), lo = rn(residual); returns (packed hi pair01, hi pair23) ...
    __nv_bfloat16 h0 = __float2bfloat16_rn(v.x);
    __nv_bfloat16 h1 = __float2bfloat16_rn(v.y);
    __nv_bfloat16 h2 = __float2bfloat16_rn(v.z);
    __nv_bfloat16 h3 = __float2bfloat16_rn(v.w);
    __nv_bfloat162 p0 = __halves2bfloat162(h0, h1);
    __nv_bfloat162 p1 = __halves2bfloat162(h2, h3);
    return make_uint2(*(uint32_t*)&p0, *(uint32_t*)&p1);
}

__global__ void __launch_bounds__(256)
k_gemm_mma(const float* __restrict__ A_ext, const float* __restrict__ W) {
    extern __shared__ __nv_bfloat16 sm[];
    const float* A = A_ext ? A_ext : g_agg;
    int tid = threadIdx.x;
    int wid = tid >> 5, lane = tid & 31;
    int row0 = blockIdx.x * 128;

    // ---- fill A hi/lo: t -> (r = t>>5, quad q = t&31) ----
    for (int t = tid; t < 4096; t += 256) {
        int q = t & 31, r = t >> 5;
        int grow = row0 + r;
        float4 v = make_float4(0.f, 0.f, 0.f, 0.f);
        if (grow < NN) v = *(const float4*)&A[(size_t)grow * DD + q * 4];
        float4 hi4;
        uint2 hu = split_pack(v);
        __nv_bfloat162 h01 = *(__nv_bfloat162*)&hu.x;
        __nv_bfloat162 h23 = *(__nv_bfloat162*)&hu.y;
        hi4.x = __bfloat162float(__low2bfloat16(h01));
        hi4.y = __bfloat162float(__high2bfloat16(h01));
        hi4.z = __bfloat162float(__low2bfloat16(h23));
        hi4.w = __bfloat162float(__high2bfloat16(h23));
        uint2 lu = split_pack(make_float4(v.x - hi4.x, v.y - hi4.y,
                                          v.z - hi4.z, v.w - hi4.w));
        *(uint2*)&sm[AH_OFF + r * ASTR + q * 4] = hu;
        *(uint2*)&sm[AL_OFF + r * ASTR + q * 4] = lu;
    }

    // ---- fill B = W^T hi/lo: Bs[n][k] from W[k*DD+n]; n fastest for coalescing --
    for (int t = tid; t < 4096; t += 256) {
        int n = t & 127, q = t >> 7;  // q: 0..31, covers k quad
        int k0 = q * 4;
        float4 v = make_float4(W[(k0 + 0) * DD + n], W[(k0 + 1) * DD + n],
                               W[(k0 + 2) * DD + n], W[(k0 + 3) * DD + n]);
        float4 hi4;
        uint2 hu = split_pack(v);
        __nv_bfloat162 h01 = *(__nv_bfloat162*)&hu.x;
        __nv_bfloat162 h23 = *(__nv_bfloat162*)&hu.y;
        hi4.x = __bfloat162float(__low2bfloat16(h01));
        hi4.y = __bfloat162float(__high2bfloat16(h01));
        hi4.z = __bfloat162float(__low2bfloat16(h23));
        hi4.w = __bfloat162float(__high2bfloat16(h23));
        uint2 lu = split_pack(make_float4(v.x - hi4.x, v.y - hi4.y,
                                          v.z - hi4.z, v.w - hi4.w));
        *(uint2*)&sm[BH_OFF + n * ASTR + k0] = hu;
        *(uint2*)&sm[BL_OFF + n * ASTR + k0] = lu;
    }
    __syncthreads();

    int wm = (wid >> 2) * 64;   // warp row origin within CTA tile
    int wn = (wid & 3) * 32;    // warp col origin

    float d[4][4][4];
    #pragma unroll
    for (int i = 0; i < 4; i++)
        #pragma unroll
        for (int j = 0; j < 4; j++)
            #pragma unroll
            for (int r = 0; r < 4; r++) d[i][j][r] = 0.f;

    uint32_t sbase = smem_u32(sm);

    #pragma unroll
    for (int kc = 0; kc < 8; kc++) {
        int k0 = kc * 16;
        uint32_t ah[4][4], al[4][4], bh[4][2], bl[4][2];
        // A fragments: 4 m16 tiles
        #pragma unroll
        for (int i = 0; i < 4; i++) {
            int r = wm + 16 * i + (lane & 15);
            int c = k0 + (lane >> 4) * 8;
            uint32_t ad = sbase + (uint32_t)(AH_OFF + r * ASTR + c) * 2;
            ldsm_x4(ah[i][0], ah[i][1], ah[i][2], ah[i][3], ad);
            ad = sbase + (uint32_t)(AL_OFF + r * ASTR + c) * 2;
            ldsm_x4(al[i][0], al[i][1], al[i][2], al[i][3], ad);
        }
        // B fragments: 2 ldmatrix.x4 cover 4 n8 tiles (hi), 2 more (lo)
        #pragma unroll
        for (int jj = 0; jj < 2; jj++) {
            int n = wn + 16 * jj + (lane & 15);
            int c = k0 + (lane >> 4) * 8;
            uint32_t r0, r1, r2, r3;
            uint32_t ad = sbase + (uint32_t)(BH_OFF + n * ASTR + c) * 2;
            ldsm_x4(r0, r1, r2, r3, ad);
            bh[2 * jj][0] = r0; bh[2 * jj + 1][0] = r1;
            bh[2 * jj][1] = r2; bh[2 * jj + 1][1] = r3;
            ad = sbase + (uint32_t)(BL_OFF + n * ASTR + c) * 2;
            ldsm_x4(r0, r1, r2, r3, ad);
            bl[2 * jj][0] = r0; bl[2 * jj + 1][0] = r1;
            bl[2 * jj][1] = r2; bl[2 * jj + 1][1] = r3;
        }
        #pragma unroll
        for (int i = 0; i < 4; i++)
            #pragma unroll
            for (int j = 0; j < 4; j++) {
                mma_bf16(d[i][j], ah[i], bh[j]);
                mma_bf16(d[i][j], ah[i], bl[j]);
                mma_bf16(d[i][j], al[i], bh[j]);
            }
    }

    // ---- epilogue: fp32 accum -> fp16 g_h ----
    int rr = lane >> 2;
    int cc = 2 * (lane & 3);
    #pragma unroll
    for (int i = 0; i < 4; i++) {
        int r_lo = row0 + wm + 16 * i + rr;
        int r_hi = r_lo + 8;
        #pragma unroll
        for (int j = 0; j < 4; j++) {
            int col = wn + 8 * j + cc;
            if (r_lo < NN) {
                __half2 h = __floats2half2_rn(d[i][j][0], d[i][j][1]);
                *(__half2*)&g_h[(size_t)r_lo * DD + col] = h;
            }
            if (r_hi < NN) {
                __half2 h = __floats2half2_rn(d[i][j][2], d[i][j][3]);
                *(__half2*)&g_h[(size_t)r_hi * DD + col] = h;
            }
        }
    }
}

// ---------------- aggregation: agg[i] = relu(sum_e h16[src]*norm + h16[i]*dinv^2 + b)
__device__ __forceinline__ float4 cvt_h4(uint2 v) {
    __half2 a = *(__half2*)&v.x;
    __half2 b = *(__half2*)&v.y;
    float2 fa = __half22float2(a);
    float2 fb = __half22float2(b);
    return make_float4(fa.x, fa.y, fb.x, fb.y);
}

__global__ void __launch_bounds__(256) k_aggregate(const float* __restrict__ bias) {
    int node = blockIdx.x * 8 + (threadIdx.x >> 5);
    if (node >= NN) return;
    int lane = threadIdx.x & 31;
    const uint2* h2 = (const uint2*)g_h;

    float di = g_dinv[node];
    float w0 = di * di;
    float4 self = cvt_h4(h2[(size_t)node * 32 + lane]);
    float4 bb = ((const float4*)bias)[lane];
    float4 acc;
    acc.x = fmaf(self.x, w0, bb.x);
    acc.y = fmaf(self.y, w0, bb.y);
    acc.z = fmaf(self.z, w0, bb.z);
    acc.w = fmaf(self.w, w0, bb.w);

    int s = g_rowptr[node], e = g_rowptr[node + 1];
    #pragma unroll 4
    for (int j = s; j < e; j++) {
        int u = g_csrc[j];
        float w = g_cnorm[j];
        float4 v = cvt_h4(h2[(size_t)u * 32 + lane]);
        acc.x = fmaf(v.x, w, acc.x);
        acc.y = fmaf(v.y, w, acc.y);
        acc.z = fmaf(v.z, w, acc.z);
        acc.w = fmaf(v.w, w, acc.w);
    }
    acc.x = fmaxf(acc.x, 0.f);
    acc.y = fmaxf(acc.y, 0.f);
    acc.z = fmaxf(acc.z, 0.f);
    acc.w = fmaxf(acc.w, 0.f);
    ((float4*)g_agg)[(size_t)node * 32 + lane] = acc;
}

// ---------------- pool (mean per graph) + classifier ----------------
__global__ void __launch_bounds__(128) k_pool_cls(const float* __restrict__ Wc,
                                                  const float* __restrict__ bc,
                                                  const float* __restrict__ Wo,
                                                  const float* __restrict__ bo,
                                                  float* __restrict__ out) {
    __shared__ float pooled[DD];
    __shared__ float zs[HH];
    int g = blockIdx.x, c = threadIdx.x;
    int s = g_gptr[g], e = g_gptr[g + 1];
    float acc = 0.f;
    for (int i = s; i < e; i++) acc += g_agg[(size_t)i * DD + c];
    pooled[c] = acc / fmaxf((float)(e - s), 1.0f);
    __syncthreads();
    if (c < HH) {
        float z = bc[c];
        #pragma unroll
        for (int dd = 0; dd < DD; dd++) z = fmaf(pooled[dd], Wc[dd * HH + c], z);
        z = fmaxf(z, 0.f);
        zs[c] = z * Wo[c];
    }
    __syncthreads();
    if (c == 0) {
        float r = bo[0];
        #pragma unroll
        for (int h = 0; h < HH; h++) r += zs[h];
        out[g] = r;
    }
}

// ---------------- launch ----------------
extern "C" void kernel_launch(void* const* d_in, const int* in_sizes, int n_in,
                              void* d_out, int out_size) {
    const float* x  = (const float*)d_in[0];
    const int*   ei = (const int*)d_in[1];      // [2, E] int32
    const int*   batch = (const int*)d_in[2];
    const float* W1 = (const float*)d_in[3];
    const float* b1 = (const float*)d_in[4];
    const float* W2 = (const float*)d_in[5];
    const float* b2 = (const float*)d_in[6];
    const float* W3 = (const float*)d_in[7];
    const float* b3 = (const float*)d_in[8];
    const float* Wc = (const float*)d_in[9];
    const float* bc = (const float*)d_in[10];
    const float* Wo = (const float*)d_in[11];
    const float* bo = (const float*)d_in[12];
    float* out = (float*)d_out;

    const int* src = ei;
    const int* dst = ei + EE;

    cudaFuncSetAttribute(k_gemm_mma, cudaFuncAttributeMaxDynamicSharedMemorySize,
                         GSMEM_BYTES);

    const int NB_N = (NN + 255) / 256;
    const int NB_E = (EE + 255) / 256;

    // graph structure (once per call)
    k_init_nodes<<<NB_N, 256>>>();
    k_hist<<<NB_E, 256>>>(dst);
    k_dinv<<<NB_N, 256>>>();
    k_scan_rows<<<1, 1024>>>();
    k_gptr<<<1, 512>>>(batch);
    k_fill<<<NB_E, 256>>>(src, dst);

    const int NB_G = (NN + 127) / 128;    // gemm blocks
    const int NB_A = (NN + 7) / 8;        // aggregate blocks

    // layer 1 (reads x)
    k_gemm_mma<<<NB_G, 256, GSMEM_BYTES>>>(x, W1);
    k_aggregate<<<NB_A, 256>>>(b1);
    // layer 2
    k_gemm_mma<<<NB_G, 256, GSMEM_BYTES>>>(nullptr, W2);
    k_aggregate<<<NB_A, 256>>>(b2);
    // layer 3
    k_gemm_mma<<<NB_G, 256, GSMEM_BYTES>>>(nullptr, W3);
    k_aggregate<<<NB_A, 256>>>(b3);

    // pool + classifier
    k_pool_cls<<<GG, 128>>>(Wc, bc, Wo, bo, out);
}

// round 4
// speedup vs baseline: 1.2471x; 1.1143x over previous
#include <cuda_runtime.h>
#include <cuda_bf16.h>
#include <cuda_fp16.h>
#include <cstdint>

// Problem constants (fixed by the dataset)
#define NN 50000
#define EE 800000
#define DD 128
#define HH 64
#define GG 512
#define NB_SCAN ((NN + 1023) / 1024)   // 49

// ---------------- device scratch (static allocation only) ----------------
__device__ __half g_h[(size_t)NN * DD];    // dinv-scaled GEMM output (fp16)
__device__ float  g_agg[(size_t)NN * DD];  // aggregated (relu'd) layer output, fp32
__device__ float  g_dinv[NN];
__device__ int    g_deg[NN];               // indegree + 1 (self loop)
__device__ int    g_fill[NN];
__device__ int    g_rowptr[NN + 1];
__device__ int    g_csrc[EE];
__device__ int    g_bsum[NB_SCAN];
__device__ int    g_gptr[GG + 1];

__device__ __forceinline__ uint32_t smem_u32(const void* p) {
    uint32_t a;
    asm("{ .reg .u64 t; cvta.to.shared.u64 t, %1; cvt.u32.u64 %0, t; }"
        : "=r"(a) : "l"(p));
    return a;
}

// ---------------- prep kernels ----------------
__global__ void k_init_nodes() {
    int i = blockIdx.x * blockDim.x + threadIdx.x;
    if (i < NN) { g_deg[i] = 1; g_fill[i] = 0; }
}

__global__ void k_hist(const int* __restrict__ dst) {
    int e = blockIdx.x * blockDim.x + threadIdx.x;
    if (e < EE) atomicAdd(&g_deg[dst[e]], 1);
}

__global__ void k_dinv() {
    int i = blockIdx.x * blockDim.x + threadIdx.x;
    if (i < NN) g_dinv[i] = rsqrtf((float)g_deg[i]);  // deg >= 1 always
}

// batch is sorted: gptr[g] = lower_bound(batch, g)
__global__ void k_gptr(const int* __restrict__ batch) {
    int g = threadIdx.x;  // 512 threads, 1 block
    int lo = 0, hi = NN;
    while (lo < hi) {
        int m = (lo + hi) >> 1;
        if (batch[m] < g) lo = m + 1; else hi = m;
    }
    g_gptr[g] = lo;
    if (g == 0) g_gptr[GG] = NN;
}

// ---- 3-phase multi-block exclusive scan of (deg-1) into rowptr ----
__global__ void __launch_bounds__(1024) k_scan1() {
    __shared__ int wsum[32];
    int tid = threadIdx.x, lane = tid & 31, wid = tid >> 5;
    int i = blockIdx.x * 1024 + tid;
    int x = (i < NN) ? (g_deg[i] - 1) : 0;
    #pragma unroll
    for (int off = 1; off < 32; off <<= 1) {
        int y = __shfl_up_sync(0xffffffff, x, off);
        if (lane >= off) x += y;
    }
    if (lane == 31) wsum[wid] = x;
    __syncthreads();
    if (wid == 0) {
        int w = wsum[lane];
        #pragma unroll
        for (int off = 1; off < 32; off <<= 1) {
            int y = __shfl_up_sync(0xffffffff, w, off);
            if (lane >= off) w += y;
        }
        wsum[lane] = w;
    }
    __syncthreads();
    int incl = x + (wid > 0 ? wsum[wid - 1] : 0);
    if (i < NN) g_rowptr[i + 1] = incl;
    if (tid == 1023) g_bsum[blockIdx.x] = incl;
}

__global__ void k_scan2() {
    __shared__ int s[NB_SCAN];
    int tid = threadIdx.x;
    if (tid < NB_SCAN) s[tid] = g_bsum[tid];
    __syncthreads();
    if (tid == 0) {
        int run = 0;
        #pragma unroll
        for (int k = 0; k < NB_SCAN; k++) { int t = s[k]; s[k] = run; run += t; }
    }
    __syncthreads();
    if (tid < NB_SCAN) g_bsum[tid] = s[tid];
}

__global__ void __launch_bounds__(1024) k_scan3() {
    int i = blockIdx.x * 1024 + threadIdx.x;
    if (i < NN) g_rowptr[i + 1] += g_bsum[blockIdx.x];
    if (i == 0) g_rowptr[0] = 0;
}

__global__ void k_fill(const int* __restrict__ src, const int* __restrict__ dst) {
    int e = blockIdx.x * blockDim.x + threadIdx.x;
    if (e >= EE) return;
    int s = src[e], d = dst[e];
    int p = g_rowptr[d] + atomicAdd(&g_fill[d], 1);
    g_csrc[p] = s;
}

// ---------------- HMMA GEMM: g_h[N,128](fp16) = dinv * (A[N,128] @ W[128,128]) --
// bf16 hi/lo split, 3 mma products, fp32 accum. 256 thr = 8 warps (2x4), each
// warp computes a 64x32 tile via m16n8k16 mma.sync + ldmatrix.
#define ASTR 136                       // bf16 row stride (17*8; conflict-free ldmatrix)
#define AH_OFF 0
#define AL_OFF (128 * ASTR)
#define BH_OFF (2 * 128 * ASTR)
#define BL_OFF (3 * 128 * ASTR)
#define GSMEM_BYTES (4 * 128 * ASTR * 2)   // 139264

__device__ __forceinline__ void ldsm_x4(uint32_t& r0, uint32_t& r1,
                                        uint32_t& r2, uint32_t& r3, uint32_t a) {
    asm volatile("ldmatrix.sync.aligned.m8n8.x4.shared.b16 {%0,%1,%2,%3}, [%4];"
                 : "=r"(r0), "=r"(r1), "=r"(r2), "=r"(r3) : "r"(a));
}

__device__ __forceinline__ void mma_bf16(float* d, const uint32_t* a,
                                         const uint32_t* b) {
    asm volatile(
        "mma.sync.aligned.m16n8k16.row.col.f32.bf16.bf16.f32 "
        "{%0,%1,%2,%3}, {%4,%5,%6,%7}, {%8,%9}, {%0,%1,%2,%3};"
        : "+f"(d[0]), "+f"(d[1]), "+f"(d[2]), "+f"(d[3])
        : "r"(a[0]), "r"(a[1]), "r"(a[2]), "r"(a[3]), "r"(b[0]), "r"(b[1]));
}

__device__ __forceinline__ uint2 split_pack(float4 v) {
    __nv_bfloat16 h0 = __float2bfloat16_rn(v.x);
    __nv_bfloat16 h1 = __float2bfloat16_rn(v.y);
    __nv_bfloat16 h2 = __float2bfloat16_rn(v.z);
    __nv_bfloat16 h3 = __float2bfloat16_rn(v.w);
    __nv_bfloat162 p0 = __halves2bfloat162(h0, h1);
    __nv_bfloat162 p1 = __halves2bfloat162(h2, h3);
    return make_uint2(*(uint32_t*)&p0, *(uint32_t*)&p1);
}

__global__ void __launch_bounds__(256)
k_gemm_mma(const float* __restrict__ A_ext, const float* __restrict__ W) {
    extern __shared__ __nv_bfloat16 sm[];
    const float* A = A_ext ? A_ext : g_agg;
    int tid = threadIdx.x;
    int wid = tid >> 5, lane = tid & 31;
    int row0 = blockIdx.x * 128;

    // ---- fill A hi/lo: t -> (r = t>>5, quad q = t&31) ----
    for (int t = tid; t < 4096; t += 256) {
        int q = t & 31, r = t >> 5;
        int grow = row0 + r;
        float4 v = make_float4(0.f, 0.f, 0.f, 0.f);
        if (grow < NN) v = *(const float4*)&A[(size_t)grow * DD + q * 4];
        float4 hi4;
        uint2 hu = split_pack(v);
        __nv_bfloat162 h01 = *(__nv_bfloat162*)&hu.x;
        __nv_bfloat162 h23 = *(__nv_bfloat162*)&hu.y;
        hi4.x = __bfloat162float(__low2bfloat16(h01));
        hi4.y = __bfloat162float(__high2bfloat16(h01));
        hi4.z = __bfloat162float(__low2bfloat16(h23));
        hi4.w = __bfloat162float(__high2bfloat16(h23));
        uint2 lu = split_pack(make_float4(v.x - hi4.x, v.y - hi4.y,
                                          v.z - hi4.z, v.w - hi4.w));
        *(uint2*)&sm[AH_OFF + r * ASTR + q * 4] = hu;
        *(uint2*)&sm[AL_OFF + r * ASTR + q * 4] = lu;
    }

    // ---- fill B = W^T hi/lo: Bs[n][k] from W[k*DD+n]; n fastest for coalescing --
    for (int t = tid; t < 4096; t += 256) {
        int n = t & 127, q = t >> 7;
        int k0 = q * 4;
        float4 v = make_float4(W[(k0 + 0) * DD + n], W[(k0 + 1) * DD + n],
                               W[(k0 + 2) * DD + n], W[(k0 + 3) * DD + n]);
        float4 hi4;
        uint2 hu = split_pack(v);
        __nv_bfloat162 h01 = *(__nv_bfloat162*)&hu.x;
        __nv_bfloat162 h23 = *(__nv_bfloat162*)&hu.y;
        hi4.x = __bfloat162float(__low2bfloat16(h01));
        hi4.y = __bfloat162float(__high2bfloat16(h01));
        hi4.z = __bfloat162float(__low2bfloat16(h23));
        hi4.w = __bfloat162float(__high2bfloat16(h23));
        uint2 lu = split_pack(make_float4(v.x - hi4.x, v.y - hi4.y,
                                          v.z - hi4.z, v.w - hi4.w));
        *(uint2*)&sm[BH_OFF + n * ASTR + k0] = hu;
        *(uint2*)&sm[BL_OFF + n * ASTR + k0] = lu;
    }
    __syncthreads();

    int wm = (wid >> 2) * 64;   // warp row origin within CTA tile
    int wn = (wid & 3) * 32;    // warp col origin

    float d[4][4][4];
    #pragma unroll
    for (int i = 0; i < 4; i++)
        #pragma unroll
        for (int j = 0; j < 4; j++)
            #pragma unroll
            for (int r = 0; r < 4; r++) d[i][j][r] = 0.f;

    uint32_t sbase = smem_u32(sm);

    #pragma unroll
    for (int kc = 0; kc < 8; kc++) {
        int k0 = kc * 16;
        uint32_t ah[4][4], al[4][4], bh[4][2], bl[4][2];
        #pragma unroll
        for (int i = 0; i < 4; i++) {
            int r = wm + 16 * i + (lane & 15);
            int c = k0 + (lane >> 4) * 8;
            uint32_t ad = sbase + (uint32_t)(AH_OFF + r * ASTR + c) * 2;
            ldsm_x4(ah[i][0], ah[i][1], ah[i][2], ah[i][3], ad);
            ad = sbase + (uint32_t)(AL_OFF + r * ASTR + c) * 2;
            ldsm_x4(al[i][0], al[i][1], al[i][2], al[i][3], ad);
        }
        #pragma unroll
        for (int jj = 0; jj < 2; jj++) {
            int n = wn + 16 * jj + (lane & 15);
            int c = k0 + (lane >> 4) * 8;
            uint32_t r0, r1, r2, r3;
            uint32_t ad = sbase + (uint32_t)(BH_OFF + n * ASTR + c) * 2;
            ldsm_x4(r0, r1, r2, r3, ad);
            bh[2 * jj][0] = r0; bh[2 * jj + 1][0] = r1;
            bh[2 * jj][1] = r2; bh[2 * jj + 1][1] = r3;
            ad = sbase + (uint32_t)(BL_OFF + n * ASTR + c) * 2;
            ldsm_x4(r0, r1, r2, r3, ad);
            bl[2 * jj][0] = r0; bl[2 * jj + 1][0] = r1;
            bl[2 * jj][1] = r2; bl[2 * jj + 1][1] = r3;
        }
        #pragma unroll
        for (int i = 0; i < 4; i++)
            #pragma unroll
            for (int j = 0; j < 4; j++) {
                mma_bf16(d[i][j], ah[i], bh[j]);
                mma_bf16(d[i][j], ah[i], bl[j]);
                mma_bf16(d[i][j], al[i], bh[j]);
            }
    }

    // ---- epilogue: scale by dinv[row], fp32 -> fp16 g_h ----
    int rr = lane >> 2;
    int cc = 2 * (lane & 3);
    #pragma unroll
    for (int i = 0; i < 4; i++) {
        int r_lo = row0 + wm + 16 * i + rr;
        int r_hi = r_lo + 8;
        float di_lo = (r_lo < NN) ? g_dinv[r_lo] : 0.f;
        float di_hi = (r_hi < NN) ? g_dinv[r_hi] : 0.f;
        #pragma unroll
        for (int j = 0; j < 4; j++) {
            int col = wn + 8 * j + cc;
            if (r_lo < NN) {
                __half2 h = __floats2half2_rn(d[i][j][0] * di_lo, d[i][j][1] * di_lo);
                *(__half2*)&g_h[(size_t)r_lo * DD + col] = h;
            }
            if (r_hi < NN) {
                __half2 h = __floats2half2_rn(d[i][j][2] * di_hi, d[i][j][3] * di_hi);
                *(__half2*)&g_h[(size_t)r_hi * DD + col] = h;
            }
        }
    }
}

// ------- aggregation: agg[d] = relu(dinv[d]*(sum_src h'[s] + h'[d]) + b) -------
__device__ __forceinline__ float4 cvt_h4(uint2 v) {
    __half2 a = *(__half2*)&v.x;
    __half2 b = *(__half2*)&v.y;
    float2 fa = __half22float2(a);
    float2 fb = __half22float2(b);
    return make_float4(fa.x, fa.y, fb.x, fb.y);
}

__global__ void __launch_bounds__(256) k_aggregate(const float* __restrict__ bias) {
    int node = blockIdx.x * 8 + (threadIdx.x >> 5);
    if (node >= NN) return;
    int lane = threadIdx.x & 31;
    const uint2* h2 = (const uint2*)g_h;

    float4 acc = cvt_h4(h2[(size_t)node * 32 + lane]);   // self term h'[d]

    int s = g_rowptr[node], e = g_rowptr[node + 1];
    int j = s;
    // full chunks of 8: lane-parallel index load, shfl broadcast -> 8 gathers in flight
    for (; j + 8 <= e; j += 8) {
        int myidx = (lane < 8) ? g_csrc[j + lane] : 0;
        #pragma unroll
        for (int u = 0; u < 8; u++) {
            int uu = __shfl_sync(0xffffffff, myidx, u);
            float4 v = cvt_h4(h2[(size_t)uu * 32 + lane]);
            acc.x += v.x; acc.y += v.y; acc.z += v.z; acc.w += v.w;
        }
    }
    int rem = e - j;
    if (rem > 0) {
        int myidx = (lane < rem) ? g_csrc[j + lane] : 0;
        #pragma unroll
        for (int u = 0; u < 7; u++) {
            if (u < rem) {
                int uu = __shfl_sync(0xffffffff, myidx, u);
                float4 v = cvt_h4(h2[(size_t)uu * 32 + lane]);
                acc.x += v.x; acc.y += v.y; acc.z += v.z; acc.w += v.w;
            }
        }
    }

    float di = g_dinv[node];
    float4 bb = ((const float4*)bias)[lane];
    acc.x = fmaxf(fmaf(acc.x, di, bb.x), 0.f);
    acc.y = fmaxf(fmaf(acc.y, di, bb.y), 0.f);
    acc.z = fmaxf(fmaf(acc.z, di, bb.z), 0.f);
    acc.w = fmaxf(fmaf(acc.w, di, bb.w), 0.f);
    ((float4*)g_agg)[(size_t)node * 32 + lane] = acc;
}

// ---------------- pool (mean per graph) + classifier ----------------
__global__ void __launch_bounds__(128) k_pool_cls(const float* __restrict__ Wc,
                                                  const float* __restrict__ bc,
                                                  const float* __restrict__ Wo,
                                                  const float* __restrict__ bo,
                                                  float* __restrict__ out) {
    __shared__ float pooled[DD];
    __shared__ float zs[HH];
    int g = blockIdx.x, c = threadIdx.x;
    int s = g_gptr[g], e = g_gptr[g + 1];
    float acc = 0.f;
    for (int i = s; i < e; i++) acc += g_agg[(size_t)i * DD + c];
    pooled[c] = acc / fmaxf((float)(e - s), 1.0f);
    __syncthreads();
    if (c < HH) {
        float z = bc[c];
        #pragma unroll
        for (int dd = 0; dd < DD; dd++) z = fmaf(pooled[dd], Wc[dd * HH + c], z);
        z = fmaxf(z, 0.f);
        zs[c] = z * Wo[c];
    }
    __syncthreads();
    if (c == 0) {
        float r = bo[0];
        #pragma unroll
        for (int h = 0; h < HH; h++) r += zs[h];
        out[g] = r;
    }
}

// ---------------- launch ----------------
extern "C" void kernel_launch(void* const* d_in, const int* in_sizes, int n_in,
                              void* d_out, int out_size) {
    const float* x  = (const float*)d_in[0];
    const int*   ei = (const int*)d_in[1];      // [2, E] int32
    const int*   batch = (const int*)d_in[2];
    const float* W1 = (const float*)d_in[3];
    const float* b1 = (const float*)d_in[4];
    const float* W2 = (const float*)d_in[5];
    const float* b2 = (const float*)d_in[6];
    const float* W3 = (const float*)d_in[7];
    const float* b3 = (const float*)d_in[8];
    const float* Wc = (const float*)d_in[9];
    const float* bc = (const float*)d_in[10];
    const float* Wo = (const float*)d_in[11];
    const float* bo = (const float*)d_in[12];
    float* out = (float*)d_out;

    const int* src = ei;
    const int* dst = ei + EE;

    cudaFuncSetAttribute(k_gemm_mma, cudaFuncAttributeMaxDynamicSharedMemorySize,
                         GSMEM_BYTES);

    const int NB_N = (NN + 255) / 256;
    const int NB_E = (EE + 255) / 256;

    // graph structure (once per call)
    k_init_nodes<<<NB_N, 256>>>();
    k_hist<<<NB_E, 256>>>(dst);
    k_dinv<<<NB_N, 256>>>();
    k_scan1<<<NB_SCAN, 1024>>>();
    k_scan2<<<1, 64>>>();
    k_scan3<<<NB_SCAN, 1024>>>();
    k_gptr<<<1, 512>>>(batch);
    k_fill<<<NB_E, 256>>>(src, dst);

    const int NB_G = (NN + 127) / 128;    // gemm blocks
    const int NB_A = (NN + 7) / 8;        // aggregate blocks

    // layer 1 (reads x)
    k_gemm_mma<<<NB_G, 256, GSMEM_BYTES>>>(x, W1);
    k_aggregate<<<NB_A, 256>>>(b1);
    // layer 2
    k_gemm_mma<<<NB_G, 256, GSMEM_BYTES>>>(nullptr, W2);
    k_aggregate<<<NB_A, 256>>>(b2);
    // layer 3
    k_gemm_mma<<<NB_G, 256, GSMEM_BYTES>>>(nullptr, W3);
    k_aggregate<<<NB_A, 256>>>(b3);

    // pool + classifier
    k_pool_cls<<<GG, 128>>>(Wc, bc, Wo, bo, out);
}

// round 5
// speedup vs baseline: 1.3868x; 1.1121x over previous
#include <cuda_runtime.h>
#include <cuda_bf16.h>
#include <cuda_fp16.h>
#include <cstdint>

// Problem constants (fixed by the dataset)
#define NN 50000
#define EE 800000
#define DD 128
#define HH 64
#define GG 512
#define NB_SCAN ((NN + 1023) / 1024)   // 49

// ---------------- device scratch (static allocation only) ----------------
__device__ __nv_bfloat16 g_ahi[(size_t)NN * DD];  // layer activations, bf16 hi plane
__device__ __nv_bfloat16 g_alo[(size_t)NN * DD];  // bf16 lo plane (hi+lo ~= fp32)
__device__ __half g_h[(size_t)NN * DD];    // dinv-scaled GEMM output (fp16)
__device__ float  g_dinv[NN];
__device__ int    g_deg[NN];               // indegree + 1 (self loop)
__device__ int    g_fill[NN];
__device__ int    g_rowptr[NN + 1];
__device__ int    g_csrc[EE];
__device__ int    g_bsum[NB_SCAN];
__device__ int    g_gptr[GG + 1];
__device__ __nv_bfloat16 g_whi[3 * DD * DD];  // transposed W planes: [n][k]
__device__ __nv_bfloat16 g_wlo[3 * DD * DD];

__device__ __forceinline__ uint32_t smem_u32(const void* p) {
    uint32_t a;
    asm("{ .reg .u64 t; cvta.to.shared.u64 t, %1; cvt.u32.u64 %0, t; }"
        : "=r"(a) : "l"(p));
    return a;
}

// ---------------- prep kernels ----------------
__global__ void k_init_nodes() {
    int i = blockIdx.x * blockDim.x + threadIdx.x;
    if (i < NN) { g_deg[i] = 1; g_fill[i] = 0; }
}

__global__ void k_hist(const int* __restrict__ dst) {
    int e = blockIdx.x * blockDim.x + threadIdx.x;
    if (e < EE) atomicAdd(&g_deg[dst[e]], 1);
}

// ---- scan phase 1 (+ fused dinv) ----
__global__ void __launch_bounds__(1024) k_scan1() {
    __shared__ int wsum[32];
    int tid = threadIdx.x, lane = tid & 31, wid = tid >> 5;
    int i = blockIdx.x * 1024 + tid;
    int deg = (i < NN) ? g_deg[i] : 1;
    if (i < NN) g_dinv[i] = rsqrtf((float)deg);
    int x = (i < NN) ? (deg - 1) : 0;
    #pragma unroll
    for (int off = 1; off < 32; off <<= 1) {
        int y = __shfl_up_sync(0xffffffff, x, off);
        if (lane >= off) x += y;
    }
    if (lane == 31) wsum[wid] = x;
    __syncthreads();
    if (wid == 0) {
        int w = wsum[lane];
        #pragma unroll
        for (int off = 1; off < 32; off <<= 1) {
            int y = __shfl_up_sync(0xffffffff, w, off);
            if (lane >= off) w += y;
        }
        wsum[lane] = w;
    }
    __syncthreads();
    int incl = x + (wid > 0 ? wsum[wid - 1] : 0);
    if (i < NN) g_rowptr[i + 1] = incl;
    if (tid == 1023) g_bsum[blockIdx.x] = incl;
}

// ---- scan phase 2 (49 block sums, 2-warp scan) + fused gptr (batch sorted) ----
__global__ void __launch_bounds__(512) k_scan2_gptr(const int* __restrict__ batch) {
    __shared__ int w0sum;
    int tid = threadIdx.x, lane = tid & 31, wid = tid >> 5;
    if (tid < 64) {
        int v = (tid < NB_SCAN) ? g_bsum[tid] : 0;
        int x = v;
        #pragma unroll
        for (int off = 1; off < 32; off <<= 1) {
            int y = __shfl_up_sync(0xffffffff, x, off);
            if (lane >= off) x += y;
        }
        if (tid == 31) w0sum = x;
        __syncwarp();
    }
    __syncthreads();
    if (tid < 64) {
        int v = (tid < NB_SCAN) ? g_bsum[tid] : 0;
        int x = v;
        #pragma unroll
        for (int off = 1; off < 32; off <<= 1) {
            int y = __shfl_up_sync(0xffffffff, x, off);
            if (lane >= off) x += y;
        }
        if (wid == 1) x += w0sum;
        if (tid < NB_SCAN) g_bsum[tid] = x - v;   // exclusive
    }
    // gptr: lower_bound over sorted batch
    int g = tid;  // 512 threads == GG
    int lo = 0, hi = NN;
    while (lo < hi) {
        int m = (lo + hi) >> 1;
        if (batch[m] < g) lo = m + 1; else hi = m;
    }
    g_gptr[g] = lo;
    if (g == 0) g_gptr[GG] = NN;
}

__global__ void __launch_bounds__(1024) k_scan3() {
    int i = blockIdx.x * 1024 + threadIdx.x;
    if (i < NN) g_rowptr[i + 1] += g_bsum[blockIdx.x];
    if (i == 0) g_rowptr[0] = 0;
}

__global__ void k_fill(const int* __restrict__ src, const int* __restrict__ dst) {
    int e = blockIdx.x * blockDim.x + threadIdx.x;
    if (e >= EE) return;
    int s = src[e], d = dst[e];
    int p = g_rowptr[d] + atomicAdd(&g_fill[d], 1);
    g_csrc[p] = s;
}

// ---------------- split helpers ----------------
__device__ __forceinline__ void split4(float4 v, uint2& hu, uint2& lu) {
    __nv_bfloat16 h0 = __float2bfloat16_rn(v.x);
    __nv_bfloat16 h1 = __float2bfloat16_rn(v.y);
    __nv_bfloat16 h2 = __float2bfloat16_rn(v.z);
    __nv_bfloat16 h3 = __float2bfloat16_rn(v.w);
    __nv_bfloat16 l0 = __float2bfloat16_rn(v.x - __bfloat162float(h0));
    __nv_bfloat16 l1 = __float2bfloat16_rn(v.y - __bfloat162float(h1));
    __nv_bfloat16 l2 = __float2bfloat16_rn(v.z - __bfloat162float(h2));
    __nv_bfloat16 l3 = __float2bfloat16_rn(v.w - __bfloat162float(h3));
    __nv_bfloat162 hp0 = __halves2bfloat162(h0, h1);
    __nv_bfloat162 hp1 = __halves2bfloat162(h2, h3);
    __nv_bfloat162 lp0 = __halves2bfloat162(l0, l1);
    __nv_bfloat162 lp1 = __halves2bfloat162(l2, l3);
    hu = make_uint2(*(uint32_t*)&hp0, *(uint32_t*)&hp1);
    lu = make_uint2(*(uint32_t*)&lp0, *(uint32_t*)&lp1);
}

// split x into g_ahi/g_alo (layer-1 A operand)
__global__ void __launch_bounds__(256) k_splitx(const float* __restrict__ x) {
    int idx = blockIdx.x * 256 + threadIdx.x;        // one float4 per thread
    if (idx >= NN * DD / 4) return;
    float4 v = ((const float4*)x)[idx];
    uint2 hu, lu;
    split4(v, hu, lu);
    ((uint2*)g_ahi)[idx] = hu;
    ((uint2*)g_alo)[idx] = lu;
}

// split all 3 weight matrices into transposed [n][k] hi/lo planes
__global__ void __launch_bounds__(256) k_splitw_all(const float* __restrict__ W1,
                                                    const float* __restrict__ W2,
                                                    const float* __restrict__ W3) {
    int idx = blockIdx.x * 256 + threadIdx.x;   // 0 .. 3*16384
    if (idx >= 3 * DD * DD) return;
    int layer = idx >> 14;
    int r = idx & 16383;
    int k = r >> 7, n = r & 127;
    const float* W = (layer == 0) ? W1 : (layer == 1) ? W2 : W3;
    float v = W[k * DD + n];                     // coalesced over n
    __nv_bfloat16 h = __float2bfloat16_rn(v);
    __nv_bfloat16 l = __float2bfloat16_rn(v - __bfloat162float(h));
    g_whi[layer * DD * DD + n * DD + k] = h;     // transposed scatter (tiny)
    g_wlo[layer * DD * DD + n * DD + k] = l;
}

// ---------------- HMMA GEMM: g_h[N,128](fp16) = dinv * (A @ W) ----------------
// A and B pre-split bf16 hi/lo planes; fill is pure copy. 256 thr = 8 warps
// (2x4), each warp computes 64x32 via m16n8k16 mma.sync + ldmatrix.
#define ASTR 136                       // bf16 row stride (17*8; conflict-free ldmatrix)
#define AH_OFF 0
#define AL_OFF (128 * ASTR)
#define BH_OFF (2 * 128 * ASTR)
#define BL_OFF (3 * 128 * ASTR)
#define GSMEM_BYTES (4 * 128 * ASTR * 2)   // 139264

__device__ __forceinline__ void ldsm_x4(uint32_t& r0, uint32_t& r1,
                                        uint32_t& r2, uint32_t& r3, uint32_t a) {
    asm volatile("ldmatrix.sync.aligned.m8n8.x4.shared.b16 {%0,%1,%2,%3}, [%4];"
                 : "=r"(r0), "=r"(r1), "=r"(r2), "=r"(r3) : "r"(a));
}

__device__ __forceinline__ void mma_bf16(float* d, const uint32_t* a,
                                         const uint32_t* b) {
    asm volatile(
        "mma.sync.aligned.m16n8k16.row.col.f32.bf16.bf16.f32 "
        "{%0,%1,%2,%3}, {%4,%5,%6,%7}, {%8,%9}, {%0,%1,%2,%3};"
        : "+f"(d[0]), "+f"(d[1]), "+f"(d[2]), "+f"(d[3])
        : "r"(a[0]), "r"(a[1]), "r"(a[2]), "r"(a[3]), "r"(b[0]), "r"(b[1]));
}

__global__ void __launch_bounds__(256)
k_gemm_mma(int layer) {
    extern __shared__ __nv_bfloat16 sm[];
    int tid = threadIdx.x;
    int wid = tid >> 5, lane = tid & 31;
    int row0 = blockIdx.x * 128;
    const __nv_bfloat16* whi = g_whi + layer * DD * DD;
    const __nv_bfloat16* wlo = g_wlo + layer * DD * DD;

    // ---- fill A planes: pure uint4 copy, t -> (r = t>>4, oct q = t&15) ----
    for (int t = tid; t < 2048; t += 256) {
        int q = t & 15, r = t >> 4;
        int grow = row0 + r;
        uint4 vh = make_uint4(0, 0, 0, 0), vl = make_uint4(0, 0, 0, 0);
        if (grow < NN) {
            vh = *(const uint4*)&g_ahi[(size_t)grow * DD + q * 8];
            vl = *(const uint4*)&g_alo[(size_t)grow * DD + q * 8];
        }
        *(uint4*)&sm[AH_OFF + r * ASTR + q * 8] = vh;
        *(uint4*)&sm[AL_OFF + r * ASTR + q * 8] = vl;
    }
    // ---- fill B planes ----
    for (int t = tid; t < 2048; t += 256) {
        int q = t & 15, n = t >> 4;
        uint4 vh = *(const uint4*)&whi[n * DD + q * 8];
        uint4 vl = *(const uint4*)&wlo[n * DD + q * 8];
        *(uint4*)&sm[BH_OFF + n * ASTR + q * 8] = vh;
        *(uint4*)&sm[BL_OFF + n * ASTR + q * 8] = vl;
    }
    __syncthreads();

    int wm = (wid >> 2) * 64;   // warp row origin within CTA tile
    int wn = (wid & 3) * 32;    // warp col origin

    float d[4][4][4];
    #pragma unroll
    for (int i = 0; i < 4; i++)
        #pragma unroll
        for (int j = 0; j < 4; j++)
            #pragma unroll
            for (int r = 0; r < 4; r++) d[i][j][r] = 0.f;

    uint32_t sbase = smem_u32(sm);

    #pragma unroll
    for (int kc = 0; kc < 8; kc++) {
        int k0 = kc * 16;
        uint32_t ah[4][4], al[4][4], bh[4][2], bl[4][2];
        #pragma unroll
        for (int i = 0; i < 4; i++) {
            int r = wm + 16 * i + (lane & 15);
            int c = k0 + (lane >> 4) * 8;
            uint32_t ad = sbase + (uint32_t)(AH_OFF + r * ASTR + c) * 2;
            ldsm_x4(ah[i][0], ah[i][1], ah[i][2], ah[i][3], ad);
            ad = sbase + (uint32_t)(AL_OFF + r * ASTR + c) * 2;
            ldsm_x4(al[i][0], al[i][1], al[i][2], al[i][3], ad);
        }
        #pragma unroll
        for (int jj = 0; jj < 2; jj++) {
            int n = wn + 16 * jj + (lane & 15);
            int c = k0 + (lane >> 4) * 8;
            uint32_t r0, r1, r2, r3;
            uint32_t ad = sbase + (uint32_t)(BH_OFF + n * ASTR + c) * 2;
            ldsm_x4(r0, r1, r2, r3, ad);
            bh[2 * jj][0] = r0; bh[2 * jj + 1][0] = r1;
            bh[2 * jj][1] = r2; bh[2 * jj + 1][1] = r3;
            ad = sbase + (uint32_t)(BL_OFF + n * ASTR + c) * 2;
            ldsm_x4(r0, r1, r2, r3, ad);
            bl[2 * jj][0] = r0; bl[2 * jj + 1][0] = r1;
            bl[2 * jj][1] = r2; bl[2 * jj + 1][1] = r3;
        }
        #pragma unroll
        for (int i = 0; i < 4; i++)
            #pragma unroll
            for (int j = 0; j < 4; j++) {
                mma_bf16(d[i][j], ah[i], bh[j]);
                mma_bf16(d[i][j], ah[i], bl[j]);
                mma_bf16(d[i][j], al[i], bh[j]);
            }
    }

    // ---- epilogue: scale by dinv[row], fp32 -> fp16 g_h ----
    int rr = lane >> 2;
    int cc = 2 * (lane & 3);
    #pragma unroll
    for (int i = 0; i < 4; i++) {
        int r_lo = row0 + wm + 16 * i + rr;
        int r_hi = r_lo + 8;
        float di_lo = (r_lo < NN) ? g_dinv[r_lo] : 0.f;
        float di_hi = (r_hi < NN) ? g_dinv[r_hi] : 0.f;
        #pragma unroll
        for (int j = 0; j < 4; j++) {
            int col = wn + 8 * j + cc;
            if (r_lo < NN) {
                __half2 h = __floats2half2_rn(d[i][j][0] * di_lo, d[i][j][1] * di_lo);
                *(__half2*)&g_h[(size_t)r_lo * DD + col] = h;
            }
            if (r_hi < NN) {
                __half2 h = __floats2half2_rn(d[i][j][2] * di_hi, d[i][j][3] * di_hi);
                *(__half2*)&g_h[(size_t)r_hi * DD + col] = h;
            }
        }
    }
}

// ------- aggregation: a[d] = relu(dinv[d]*(sum_src h'[s] + h'[d]) + b) -> planes --
__device__ __forceinline__ float4 cvt_h4(uint2 v) {
    __half2 a = *(__half2*)&v.x;
    __half2 b = *(__half2*)&v.y;
    float2 fa = __half22float2(a);
    float2 fb = __half22float2(b);
    return make_float4(fa.x, fa.y, fb.x, fb.y);
}

__global__ void __launch_bounds__(256) k_aggregate(const float* __restrict__ bias) {
    int node = blockIdx.x * 8 + (threadIdx.x >> 5);
    if (node >= NN) return;
    int lane = threadIdx.x & 31;
    const uint2* h2 = (const uint2*)g_h;

    float4 acc = cvt_h4(h2[(size_t)node * 32 + lane]);   // self term h'[d]

    int s = g_rowptr[node], e = g_rowptr[node + 1];
    int j = s;
    // chunks of 16: lane-parallel index load, shfl broadcast -> 16 gathers in flight
    for (; j + 16 <= e; j += 16) {
        int myidx = (lane < 16) ? g_csrc[j + lane] : 0;
        #pragma unroll
        for (int u = 0; u < 16; u++) {
            int uu = __shfl_sync(0xffffffff, myidx, u);
            float4 v = cvt_h4(h2[(size_t)uu * 32 + lane]);
            acc.x += v.x; acc.y += v.y; acc.z += v.z; acc.w += v.w;
        }
    }
    int rem = e - j;
    if (rem > 0) {
        int myidx = (lane < rem) ? g_csrc[j + lane] : 0;
        #pragma unroll
        for (int u = 0; u < 15; u++) {
            if (u < rem) {
                int uu = __shfl_sync(0xffffffff, myidx, u);
                float4 v = cvt_h4(h2[(size_t)uu * 32 + lane]);
                acc.x += v.x; acc.y += v.y; acc.z += v.z; acc.w += v.w;
            }
        }
    }

    float di = g_dinv[node];
    float4 bb = ((const float4*)bias)[lane];
    float4 r;
    r.x = fmaxf(fmaf(acc.x, di, bb.x), 0.f);
    r.y = fmaxf(fmaf(acc.y, di, bb.y), 0.f);
    r.z = fmaxf(fmaf(acc.z, di, bb.z), 0.f);
    r.w = fmaxf(fmaf(acc.w, di, bb.w), 0.f);
    uint2 hu, lu;
    split4(r, hu, lu);
    ((uint2*)g_ahi)[(size_t)node * 32 + lane] = hu;
    ((uint2*)g_alo)[(size_t)node * 32 + lane] = lu;
}

// ---------------- pool (mean per graph) + classifier ----------------
__global__ void __launch_bounds__(128) k_pool_cls(const float* __restrict__ Wc,
                                                  const float* __restrict__ bc,
                                                  const float* __restrict__ Wo,
                                                  const float* __restrict__ bo,
                                                  float* __restrict__ out) {
    __shared__ float pooled[DD];
    __shared__ float zs[HH];
    int g = blockIdx.x, c = threadIdx.x;
    int s = g_gptr[g], e = g_gptr[g + 1];
    float acc = 0.f;
    for (int i = s; i < e; i++)
        acc += __bfloat162float(g_ahi[(size_t)i * DD + c]) +
               __bfloat162float(g_alo[(size_t)i * DD + c]);
    pooled[c] = acc / fmaxf((float)(e - s), 1.0f);
    __syncthreads();
    if (c < HH) {
        float z = bc[c];
        #pragma unroll
        for (int dd = 0; dd < DD; dd++) z = fmaf(pooled[dd], Wc[dd * HH + c], z);
        z = fmaxf(z, 0.f);
        zs[c] = z * Wo[c];
    }
    __syncthreads();
    if (c == 0) {
        float r = bo[0];
        #pragma unroll
        for (int h = 0; h < HH; h++) r += zs[h];
        out[g] = r;
    }
}

// ---------------- launch ----------------
extern "C" void kernel_launch(void* const* d_in, const int* in_sizes, int n_in,
                              void* d_out, int out_size) {
    const float* x  = (const float*)d_in[0];
    const int*   ei = (const int*)d_in[1];      // [2, E] int32
    const int*   batch = (const int*)d_in[2];
    const float* W1 = (const float*)d_in[3];
    const float* b1 = (const float*)d_in[4];
    const float* W2 = (const float*)d_in[5];
    const float* b2 = (const float*)d_in[6];
    const float* W3 = (const float*)d_in[7];
    const float* b3 = (const float*)d_in[8];
    const float* Wc = (const float*)d_in[9];
    const float* bc = (const float*)d_in[10];
    const float* Wo = (const float*)d_in[11];
    const float* bo = (const float*)d_in[12];
    float* out = (float*)d_out;

    const int* src = ei;
    const int* dst = ei + EE;

    cudaFuncSetAttribute(k_gemm_mma, cudaFuncAttributeMaxDynamicSharedMemorySize,
                         GSMEM_BYTES);

    const int NB_N = (NN + 255) / 256;
    const int NB_E = (EE + 255) / 256;

    // graph structure (once per call)
    k_init_nodes<<<NB_N, 256>>>();
    k_hist<<<NB_E, 256>>>(dst);
    k_scan1<<<NB_SCAN, 1024>>>();
    k_scan2_gptr<<<1, 512>>>(batch);
    k_scan3<<<NB_SCAN, 1024>>>();
    k_fill<<<NB_E, 256>>>(src, dst);

    // operand prep
    k_splitx<<<(NN * DD / 4 + 255) / 256, 256>>>(x);
    k_splitw_all<<<(3 * DD * DD + 255) / 256, 256>>>(W1, W2, W3);

    const int NB_G = (NN + 127) / 128;    // gemm blocks
    const int NB_A = (NN + 7) / 8;        // aggregate blocks

    // layer 1
    k_gemm_mma<<<NB_G, 256, GSMEM_BYTES>>>(0);
    k_aggregate<<<NB_A, 256>>>(b1);
    // layer 2
    k_gemm_mma<<<NB_G, 256, GSMEM_BYTES>>>(1);
    k_aggregate<<<NB_A, 256>>>(b2);
    // layer 3
    k_gemm_mma<<<NB_G, 256, GSMEM_BYTES>>>(2);
    k_aggregate<<<NB_A, 256>>>(b3);

    // pool + classifier
    k_pool_cls<<<GG, 128>>>(Wc, bc, Wo, bo, out);
}

// round 7
// speedup vs baseline: 1.4533x; 1.0479x over previous
#include <cuda_runtime.h>
#include <cuda_bf16.h>
#include <cuda_fp16.h>
#include <cstdint>

// Problem constants (fixed by the dataset)
#define NN 50000
#define EE 800000
#define DD 128
#define HH 64
#define GG 512
#define NB_SCAN ((NN + 1023) / 1024)   // 49

// ---------------- device scratch (static allocation only) ----------------
__device__ __nv_bfloat16 g_ahi[(size_t)NN * DD];  // layer activations, bf16 hi plane
__device__ __nv_bfloat16 g_alo[(size_t)NN * DD];  // bf16 lo plane (hi+lo ~= fp32)
__device__ __half g_h[(size_t)NN * DD];    // dinv-scaled GEMM output (fp16)
__device__ float  g_dinv[NN];
__device__ int    g_deg[NN];               // indegree + 1 (self loop)
__device__ int    g_fill[NN];
__device__ int    g_rowptr[NN + 1];
__device__ int    g_csrc[EE];
__device__ int    g_bsum[NB_SCAN];
__device__ int    g_gptr[GG + 1];
__device__ __nv_bfloat16 g_whi[3 * DD * DD];  // transposed W planes: [n][k]
__device__ __nv_bfloat16 g_wlo[3 * DD * DD];

__device__ __forceinline__ uint32_t smem_u32(const void* p) {
    uint32_t a;
    asm("{ .reg .u64 t; cvta.to.shared.u64 t, %1; cvt.u32.u64 %0, t; }"
        : "=r"(a) : "l"(p));
    return a;
}

// ---------------- prep kernels ----------------
__global__ void k_init_nodes() {
    int i = blockIdx.x * blockDim.x + threadIdx.x;
    if (i < NN) { g_deg[i] = 1; g_fill[i] = 0; }
}

__global__ void k_hist(const int* __restrict__ dst) {
    int e = blockIdx.x * blockDim.x + threadIdx.x;
    if (e < EE) atomicAdd(&g_deg[dst[e]], 1);
}

// ---- scan phase 1 (+ fused dinv) ----
__global__ void __launch_bounds__(1024) k_scan1() {
    __shared__ int wsum[32];
    int tid = threadIdx.x, lane = tid & 31, wid = tid >> 5;
    int i = blockIdx.x * 1024 + tid;
    int deg = (i < NN) ? g_deg[i] : 1;
    if (i < NN) g_dinv[i] = rsqrtf((float)deg);
    int x = (i < NN) ? (deg - 1) : 0;
    #pragma unroll
    for (int off = 1; off < 32; off <<= 1) {
        int y = __shfl_up_sync(0xffffffff, x, off);
        if (lane >= off) x += y;
    }
    if (lane == 31) wsum[wid] = x;
    __syncthreads();
    if (wid == 0) {
        int w = wsum[lane];
        #pragma unroll
        for (int off = 1; off < 32; off <<= 1) {
            int y = __shfl_up_sync(0xffffffff, w, off);
            if (lane >= off) w += y;
        }
        wsum[lane] = w;
    }
    __syncthreads();
    int incl = x + (wid > 0 ? wsum[wid - 1] : 0);
    if (i < NN) g_rowptr[i + 1] = incl;
    if (tid == 1023) g_bsum[blockIdx.x] = incl;
}

// ---- scan phase 2: tiny, 49 block sums with 2 warps ----
__global__ void __launch_bounds__(64) k_scan2() {
    __shared__ int w0sum;
    int tid = threadIdx.x, lane = tid & 31, wid = tid >> 5;
    int v = (tid < NB_SCAN) ? g_bsum[tid] : 0;
    int x = v;
    #pragma unroll
    for (int off = 1; off < 32; off <<= 1) {
        int y = __shfl_up_sync(0xffffffff, x, off);
        if (lane >= off) x += y;
    }
    if (tid == 31) w0sum = x;
    __syncthreads();
    if (wid == 1) x += w0sum;
    if (tid < NB_SCAN) g_bsum[tid] = x - v;   // exclusive
}

// ---- scan phase 3 (+ fused gptr via sorted-batch boundary detection) ----
__global__ void __launch_bounds__(1024) k_scan3_gptr(const int* __restrict__ batch) {
    int i = blockIdx.x * 1024 + threadIdx.x;
    if (i < NN) {
        g_rowptr[i + 1] += g_bsum[blockIdx.x];
        int b = batch[i];
        int pb = (i > 0) ? batch[i - 1] : -1;
        for (int g = pb + 1; g <= b; g++) g_gptr[g] = i;   // lower_bound boundaries
        if (i == NN - 1)
            for (int g = b + 1; g <= GG; g++) g_gptr[g] = NN;
    }
    if (i == 0) g_rowptr[0] = 0;
}

__global__ void k_fill(const int* __restrict__ src, const int* __restrict__ dst) {
    int e = blockIdx.x * blockDim.x + threadIdx.x;
    if (e >= EE) return;
    int s = src[e], d = dst[e];
    int p = g_rowptr[d] + atomicAdd(&g_fill[d], 1);
    g_csrc[p] = s;
}

// ---------------- split helpers ----------------
__device__ __forceinline__ void split4(float4 v, uint2& hu, uint2& lu) {
    __nv_bfloat16 h0 = __float2bfloat16_rn(v.x);
    __nv_bfloat16 h1 = __float2bfloat16_rn(v.y);
    __nv_bfloat16 h2 = __float2bfloat16_rn(v.z);
    __nv_bfloat16 h3 = __float2bfloat16_rn(v.w);
    __nv_bfloat16 l0 = __float2bfloat16_rn(v.x - __bfloat162float(h0));
    __nv_bfloat16 l1 = __float2bfloat16_rn(v.y - __bfloat162float(h1));
    __nv_bfloat16 l2 = __float2bfloat16_rn(v.z - __bfloat162float(h2));
    __nv_bfloat16 l3 = __float2bfloat16_rn(v.w - __bfloat162float(h3));
    __nv_bfloat162 hp0 = __halves2bfloat162(h0, h1);
    __nv_bfloat162 hp1 = __halves2bfloat162(h2, h3);
    __nv_bfloat162 lp0 = __halves2bfloat162(l0, l1);
    __nv_bfloat162 lp1 = __halves2bfloat162(l2, l3);
    hu = make_uint2(*(uint32_t*)&hp0, *(uint32_t*)&hp1);
    lu = make_uint2(*(uint32_t*)&lp0, *(uint32_t*)&lp1);
}

// split x into g_ahi/g_alo (layer-1 A operand)
__global__ void __launch_bounds__(256) k_splitx(const float* __restrict__ x) {
    int idx = blockIdx.x * 256 + threadIdx.x;        // one float4 per thread
    if (idx >= NN * DD / 4) return;
    float4 v = ((const float4*)x)[idx];
    uint2 hu, lu;
    split4(v, hu, lu);
    ((uint2*)g_ahi)[idx] = hu;
    ((uint2*)g_alo)[idx] = lu;
}

// split all 3 weight matrices into transposed [n][k] hi/lo planes
__global__ void __launch_bounds__(256) k_splitw_all(const float* __restrict__ W1,
                                                    const float* __restrict__ W2,
                                                    const float* __restrict__ W3) {
    int idx = blockIdx.x * 256 + threadIdx.x;   // 0 .. 3*16384
    if (idx >= 3 * DD * DD) return;
    int layer = idx >> 14;
    int r = idx & 16383;
    int k = r >> 7, n = r & 127;
    const float* W = (layer == 0) ? W1 : (layer == 1) ? W2 : W3;
    float v = W[k * DD + n];                     // coalesced over n
    __nv_bfloat16 h = __float2bfloat16_rn(v);
    __nv_bfloat16 l = __float2bfloat16_rn(v - __bfloat162float(h));
    g_whi[layer * DD * DD + n * DD + k] = h;     // transposed scatter (tiny)
    g_wlo[layer * DD * DD + n * DD + k] = l;
}

// ---------------- HMMA GEMM: g_h[N,128](fp16) = dinv * (A @ W) ----------------
// A and B pre-split bf16 hi/lo planes; fill is pure copy. 512 thr = 16 warps
// (4x4), each warp computes 32x32 via m16n8k16 mma.sync + ldmatrix.
#define ASTR 136                       // bf16 row stride (17*8; conflict-free ldmatrix)
#define AH_OFF 0
#define AL_OFF (128 * ASTR)
#define BH_OFF (2 * 128 * ASTR)
#define BL_OFF (3 * 128 * ASTR)
#define GSMEM_BYTES (4 * 128 * ASTR * 2)   // 139264

__device__ __forceinline__ void ldsm_x4(uint32_t& r0, uint32_t& r1,
                                        uint32_t& r2, uint32_t& r3, uint32_t a) {
    asm volatile("ldmatrix.sync.aligned.m8n8.x4.shared.b16 {%0,%1,%2,%3}, [%4];"
                 : "=r"(r0), "=r"(r1), "=r"(r2), "=r"(r3) : "r"(a));
}

__device__ __forceinline__ void mma_bf16(float* d, const uint32_t* a,
                                         const uint32_t* b) {
    asm volatile(
        "mma.sync.aligned.m16n8k16.row.col.f32.bf16.bf16.f32 "
        "{%0,%1,%2,%3}, {%4,%5,%6,%7}, {%8,%9}, {%0,%1,%2,%3};"
        : "+f"(d[0]), "+f"(d[1]), "+f"(d[2]), "+f"(d[3])
        : "r"(a[0]), "r"(a[1]), "r"(a[2]), "r"(a[3]), "r"(b[0]), "r"(b[1]));
}

__global__ void __launch_bounds__(512)
k_gemm_mma(int layer) {
    extern __shared__ __nv_bfloat16 sm[];
    int tid = threadIdx.x;
    int wid = tid >> 5, lane = tid & 31;
    int row0 = blockIdx.x * 128;
    const __nv_bfloat16* whi = g_whi + layer * DD * DD;
    const __nv_bfloat16* wlo = g_wlo + layer * DD * DD;

    // ---- fill A planes: pure uint4 copy, t -> (r = t>>4, oct q = t&15) ----
    for (int t = tid; t < 2048; t += 512) {
        int q = t & 15, r = t >> 4;
        int grow = row0 + r;
        uint4 vh = make_uint4(0, 0, 0, 0), vl = make_uint4(0, 0, 0, 0);
        if (grow < NN) {
            vh = *(const uint4*)&g_ahi[(size_t)grow * DD + q * 8];
            vl = *(const uint4*)&g_alo[(size_t)grow * DD + q * 8];
        }
        *(uint4*)&sm[AH_OFF + r * ASTR + q * 8] = vh;
        *(uint4*)&sm[AL_OFF + r * ASTR + q * 8] = vl;
    }
    // ---- fill B planes ----
    for (int t = tid; t < 2048; t += 512) {
        int q = t & 15, n = t >> 4;
        uint4 vh = *(const uint4*)&whi[n * DD + q * 8];
        uint4 vl = *(const uint4*)&wlo[n * DD + q * 8];
        *(uint4*)&sm[BH_OFF + n * ASTR + q * 8] = vh;
        *(uint4*)&sm[BL_OFF + n * ASTR + q * 8] = vl;
    }
    __syncthreads();

    int wm = (wid >> 2) * 32;   // warp row origin within CTA tile
    int wn = (wid & 3) * 32;    // warp col origin

    float d[2][4][4];
    #pragma unroll
    for (int i = 0; i < 2; i++)
        #pragma unroll
        for (int j = 0; j < 4; j++)
            #pragma unroll
            for (int r = 0; r < 4; r++) d[i][j][r] = 0.f;

    uint32_t sbase = smem_u32(sm);

    #pragma unroll
    for (int kc = 0; kc < 8; kc++) {
        int k0 = kc * 16;
        uint32_t ah[2][4], al[2][4], bh[4][2], bl[4][2];
        #pragma unroll
        for (int i = 0; i < 2; i++) {
            int r = wm + 16 * i + (lane & 15);
            int c = k0 + (lane >> 4) * 8;
            uint32_t ad = sbase + (uint32_t)(AH_OFF + r * ASTR + c) * 2;
            ldsm_x4(ah[i][0], ah[i][1], ah[i][2], ah[i][3], ad);
            ad = sbase + (uint32_t)(AL_OFF + r * ASTR + c) * 2;
            ldsm_x4(al[i][0], al[i][1], al[i][2], al[i][3], ad);
        }
        #pragma unroll
        for (int jj = 0; jj < 2; jj++) {
            int n = wn + 16 * jj + (lane & 15);
            int c = k0 + (lane >> 4) * 8;
            uint32_t r0, r1, r2, r3;
            uint32_t ad = sbase + (uint32_t)(BH_OFF + n * ASTR + c) * 2;
            ldsm_x4(r0, r1, r2, r3, ad);
            bh[2 * jj][0] = r0; bh[2 * jj + 1][0] = r1;
            bh[2 * jj][1] = r2; bh[2 * jj + 1][1] = r3;
            ad = sbase + (uint32_t)(BL_OFF + n * ASTR + c) * 2;
            ldsm_x4(r0, r1, r2, r3, ad);
            bl[2 * jj][0] = r0; bl[2 * jj + 1][0] = r1;
            bl[2 * jj][1] = r2; bl[2 * jj + 1][1] = r3;
        }
        #pragma unroll
        for (int i = 0; i < 2; i++)
            #pragma unroll
            for (int j = 0; j < 4; j++) {
                mma_bf16(d[i][j], ah[i], bh[j]);
                mma_bf16(d[i][j], ah[i], bl[j]);
                mma_bf16(d[i][j], al[i], bh[j]);
            }
    }

    // ---- epilogue: scale by dinv[row], fp32 -> fp16 g_h ----
    int rr = lane >> 2;
    int cc = 2 * (lane & 3);
    #pragma unroll
    for (int i = 0; i < 2; i++) {
        int r_lo = row0 + wm + 16 * i + rr;
        int r_hi = r_lo + 8;
        float di_lo = (r_lo < NN) ? g_dinv[r_lo] : 0.f;
        float di_hi = (r_hi < NN) ? g_dinv[r_hi] : 0.f;
        #pragma unroll
        for (int j = 0; j < 4; j++) {
            int col = wn + 8 * j + cc;
            if (r_lo < NN) {
                __half2 h = __floats2half2_rn(d[i][j][0] * di_lo, d[i][j][1] * di_lo);
                *(__half2*)&g_h[(size_t)r_lo * DD + col] = h;
            }
            if (r_hi < NN) {
                __half2 h = __floats2half2_rn(d[i][j][2] * di_hi, d[i][j][3] * di_hi);
                *(__half2*)&g_h[(size_t)r_hi * DD + col] = h;
            }
        }
    }
}

// ------- aggregation: a[d] = relu(dinv[d]*(sum_src h'[s] + h'[d]) + b) -> planes --
// 2 nodes per warp: each 16-lane half gathers full 256B rows with uint4 loads.
// NN = 50000 = 16 * 3125, so every block's 16 nodes are valid.
__device__ __forceinline__ void add8(float* a, uint4 v) {
    __half2* p = (__half2*)&v;
    #pragma unroll
    for (int k = 0; k < 4; k++) {
        float2 f = __half22float2(p[k]);
        a[2 * k] += f.x;
        a[2 * k + 1] += f.y;
    }
}

__global__ void __launch_bounds__(256) k_aggregate(const float* __restrict__ bias) {
    int wid = threadIdx.x >> 5, lane = threadIdx.x & 31;
    int half = lane >> 4, hl = lane & 15;
    int node = blockIdx.x * 16 + wid * 2 + half;
    const uint4* h4 = (const uint4*)g_h;

    float a[8];
    {   // self term h'[d]
        uint4 v = h4[(size_t)node * 16 + hl];
        __half2* p = (__half2*)&v;
        #pragma unroll
        for (int k = 0; k < 4; k++) {
            float2 f = __half22float2(p[k]);
            a[2 * k] = f.x;
            a[2 * k + 1] = f.y;
        }
    }

    int s = g_rowptr[node], e = g_rowptr[node + 1];
    int chunks = (e - s + 15) >> 4;
    int cmax = max(chunks, __shfl_xor_sync(0xffffffffu, chunks, 16));

    for (int t = 0; t < cmax; t++) {
        int p = s + t * 16 + hl;
        int idx = (t < chunks && p < e) ? g_csrc[p] : -1;
        #pragma unroll
        for (int u = 0; u < 16; u++) {
            int uu = __shfl_sync(0xffffffffu, idx, (half << 4) + u);
            if (uu >= 0) add8(a, h4[(size_t)uu * 16 + hl]);
        }
    }

    float di = g_dinv[node];
    const float4* b4 = (const float4*)bias;
    float4 b0 = b4[hl * 2], b1 = b4[hl * 2 + 1];
    float4 r0, r1;
    r0.x = fmaxf(fmaf(a[0], di, b0.x), 0.f);
    r0.y = fmaxf(fmaf(a[1], di, b0.y), 0.f);
    r0.z = fmaxf(fmaf(a[2], di, b0.z), 0.f);
    r0.w = fmaxf(fmaf(a[3], di, b0.w), 0.f);
    r1.x = fmaxf(fmaf(a[4], di, b1.x), 0.f);
    r1.y = fmaxf(fmaf(a[5], di, b1.y), 0.f);
    r1.z = fmaxf(fmaf(a[6], di, b1.z), 0.f);
    r1.w = fmaxf(fmaf(a[7], di, b1.w), 0.f);

    uint2 h0, l0, h1, l1;
    split4(r0, h0, l0);
    split4(r1, h1, l1);
    ((uint4*)g_ahi)[(size_t)node * 16 + hl] = make_uint4(h0.x, h0.y, h1.x, h1.y);
    ((uint4*)g_alo)[(size_t)node * 16 + hl] = make_uint4(l0.x, l0.y, l1.x, l1.y);
}

// ---------------- pool (mean per graph) + classifier ----------------
__global__ void __launch_bounds__(128) k_pool_cls(const float* __restrict__ Wc,
                                                  const float* __restrict__ bc,
                                                  const float* __restrict__ Wo,
                                                  const float* __restrict__ bo,
                                                  float* __restrict__ out) {
    __shared__ float pooled[DD];
    __shared__ float zs[HH];
    int g = blockIdx.x, c = threadIdx.x;
    int s = g_gptr[g], e = g_gptr[g + 1];
    float acc = 0.f;
    for (int i = s; i < e; i++)
        acc += __bfloat162float(g_ahi[(size_t)i * DD + c]) +
               __bfloat162float(g_alo[(size_t)i * DD + c]);
    pooled[c] = acc / fmaxf((float)(e - s), 1.0f);
    __syncthreads();
    if (c < HH) {
        float z = bc[c];
        #pragma unroll
        for (int dd = 0; dd < DD; dd++) z = fmaf(pooled[dd], Wc[dd * HH + c], z);
        z = fmaxf(z, 0.f);
        zs[c] = z * Wo[c];
    }
    __syncthreads();
    if (c == 0) {
        float r = bo[0];
        #pragma unroll
        for (int h = 0; h < HH; h++) r += zs[h];
        out[g] = r;
    }
}

// ---------------- launch ----------------
extern "C" void kernel_launch(void* const* d_in, const int* in_sizes, int n_in,
                              void* d_out, int out_size) {
    const float* x  = (const float*)d_in[0];
    const int*   ei = (const int*)d_in[1];      // [2, E] int32
    const int*   batch = (const int*)d_in[2];
    const float* W1 = (const float*)d_in[3];
    const float* b1 = (const float*)d_in[4];
    const float* W2 = (const float*)d_in[5];
    const float* b2 = (const float*)d_in[6];
    const float* W3 = (const float*)d_in[7];
    const float* b3 = (const float*)d_in[8];
    const float* Wc = (const float*)d_in[9];
    const float* bc = (const float*)d_in[10];
    const float* Wo = (const float*)d_in[11];
    const float* bo = (const float*)d_in[12];
    float* out = (float*)d_out;

    const int* src = ei;
    const int* dst = ei + EE;

    cudaFuncSetAttribute(k_gemm_mma, cudaFuncAttributeMaxDynamicSharedMemorySize,
                         GSMEM_BYTES);

    const int NB_N = (NN + 255) / 256;
    const int NB_E = (EE + 255) / 256;

    // graph structure (once per call)
    k_init_nodes<<<NB_N, 256>>>();
    k_hist<<<NB_E, 256>>>(dst);
    k_scan1<<<NB_SCAN, 1024>>>();
    k_scan2<<<1, 64>>>();
    k_scan3_gptr<<<NB_SCAN, 1024>>>(batch);
    k_fill<<<NB_E, 256>>>(src, dst);

    // operand prep
    k_splitx<<<(NN * DD / 4 + 255) / 256, 256>>>(x);
    k_splitw_all<<<(3 * DD * DD + 255) / 256, 256>>>(W1, W2, W3);

    const int NB_G = (NN + 127) / 128;    // gemm blocks
    const int NB_A = NN / 16;             // aggregate blocks (exact)

    // layer 1
    k_gemm_mma<<<NB_G, 512, GSMEM_BYTES>>>(0);
    k_aggregate<<<NB_A, 256>>>(b1);
    // layer 2
    k_gemm_mma<<<NB_G, 512, GSMEM_BYTES>>>(1);
    k_aggregate<<<NB_A, 256>>>(b2);
    // layer 3
    k_gemm_mma<<<NB_G, 512, GSMEM_BYTES>>>(2);
    k_aggregate<<<NB_A, 256>>>(b3);

    // pool + classifier
    k_pool_cls<<<GG, 128>>>(Wc, bc, Wo, bo, out);
}

// round 10
// speedup vs baseline: 1.8167x; 1.2501x over previous
#include <cuda_runtime.h>
#include <cuda_bf16.h>
#include <cuda_fp16.h>
#include <cstdint>

// Problem constants (fixed by the dataset)
#define NN 50000
#define EE 800000
#define DD 128
#define HH 64
#define GG 512
#define NB_SCAN ((NN + 1023) / 1024)   // 49

// ---------------- device scratch (static allocation only) ----------------
__device__ __half g_act[(size_t)NN * DD];  // activations: GEMM input (fp16)
__device__ __half g_h[(size_t)NN * DD];    // dinv-scaled GEMM output (fp16)
__device__ float  g_dinv[NN];
__device__ int    g_deg[NN];               // indegree + 1 (self loop)
__device__ int    g_fill[NN];
__device__ int    g_rowptr[NN + 1];
__device__ int    g_csrc[EE];
__device__ int    g_bsum[NB_SCAN];
__device__ int    g_gptr[GG + 1];
__device__ __half g_w16[3 * DD * DD];      // transposed W fp16: [layer][n][k]

__device__ __forceinline__ uint32_t smem_u32(const void* p) {
    uint32_t a;
    asm("{ .reg .u64 t; cvta.to.shared.u64 t, %1; cvt.u32.u64 %0, t; }"
        : "=r"(a) : "l"(p));
    return a;
}

// ---------------- prep kernels ----------------
__global__ void k_init_nodes() {
    int i = blockIdx.x * blockDim.x + threadIdx.x;
    if (i < NN) { g_deg[i] = 1; g_fill[i] = 0; }
}

__global__ void k_hist(const int* __restrict__ dst) {
    int e = blockIdx.x * blockDim.x + threadIdx.x;
    if (e < EE) atomicAdd(&g_deg[dst[e]], 1);
}

// ---- scan phase 1 (+ fused dinv) ----
__global__ void __launch_bounds__(1024) k_scan1() {
    __shared__ int wsum[32];
    int tid = threadIdx.x, lane = tid & 31, wid = tid >> 5;
    int i = blockIdx.x * 1024 + tid;
    int deg = (i < NN) ? g_deg[i] : 1;
    if (i < NN) g_dinv[i] = rsqrtf((float)deg);
    int x = (i < NN) ? (deg - 1) : 0;
    #pragma unroll
    for (int off = 1; off < 32; off <<= 1) {
        int y = __shfl_up_sync(0xffffffff, x, off);
        if (lane >= off) x += y;
    }
    if (lane == 31) wsum[wid] = x;
    __syncthreads();
    if (wid == 0) {
        int w = wsum[lane];
        #pragma unroll
        for (int off = 1; off < 32; off <<= 1) {
            int y = __shfl_up_sync(0xffffffff, w, off);
            if (lane >= off) w += y;
        }
        wsum[lane] = w;
    }
    __syncthreads();
    int incl = x + (wid > 0 ? wsum[wid - 1] : 0);
    if (i < NN) g_rowptr[i + 1] = incl;
    if (tid == 1023) g_bsum[blockIdx.x] = incl;
}

// ---- scan phase 3 with inline block-sum prefix (scan2 fused) + gptr ----
__global__ void __launch_bounds__(1024) k_scan3_gptr(const int* __restrict__ batch) {
    __shared__ int soff;
    int tid = threadIdx.x;
    if (tid == 0) {
        int run = 0;
        #pragma unroll
        for (int k = 0; k < NB_SCAN; k++) {     // 49 sequential adds, L2-hot
            if (k == blockIdx.x) break;
            run += g_bsum[k];
        }
        soff = run;
    }
    __syncthreads();
    int off = soff;
    int i = blockIdx.x * 1024 + tid;
    if (i < NN) {
        g_rowptr[i + 1] += off;
        int b = batch[i];
        int pb = (i > 0) ? batch[i - 1] : -1;
        for (int g = pb + 1; g <= b; g++) g_gptr[g] = i;   // lower_bound boundaries
        if (i == NN - 1)
            for (int g = b + 1; g <= GG; g++) g_gptr[g] = NN;
    }
    if (i == 0) g_rowptr[0] = 0;
}

__global__ void k_fill(const int* __restrict__ src, const int* __restrict__ dst) {
    int e = blockIdx.x * blockDim.x + threadIdx.x;
    if (e >= EE) return;
    int s = src[e], d = dst[e];
    int p = g_rowptr[d] + atomicAdd(&g_fill[d], 1);
    g_csrc[p] = s;
}

// ---- fused operand conversion: x -> g_act (fp16), W1/2/3 -> g_w16 transposed --
#define XTASKS (NN * DD / 4)                 // 1,600,000 float4s
#define XBLK ((XTASKS + 255) / 256)          // 6250
#define WBLK (3 * DD * DD / 256)             // 192

__global__ void __launch_bounds__(256) k_convert(const float* __restrict__ x,
                                                 const float* __restrict__ W1,
                                                 const float* __restrict__ W2,
                                                 const float* __restrict__ W3) {
    int b = blockIdx.x;
    if (b < XBLK) {
        int idx = b * 256 + threadIdx.x;
        if (idx < XTASKS) {
            float4 v = ((const float4*)x)[idx];
            __half2 p0 = __floats2half2_rn(v.x, v.y);
            __half2 p1 = __floats2half2_rn(v.z, v.w);
            ((uint2*)g_act)[idx] = make_uint2(*(uint32_t*)&p0, *(uint32_t*)&p1);
        }
    } else {
        int idx = (b - XBLK) * 256 + threadIdx.x;   // 0 .. 49151
        int layer = idx >> 14;
        int r = idx & 16383;
        int k = r >> 7, n = r & 127;
        const float* W = (layer == 0) ? W1 : (layer == 1) ? W2 : W3;
        g_w16[layer * DD * DD + n * DD + k] = __float2half_rn(W[k * DD + n]);
    }
}

// ---------------- HMMA GEMM: g_h[N,128](fp16) = dinv * (act @ W) --------------
// Single fp16 product. 512 thr = 16 warps (4x4), each warp 32x32 via
// m16n8k16 mma.sync + ldmatrix. 69.6KB smem -> 2 CTA/SM.
#define ASTR 136                       // fp16 row stride (17*8; conflict-free ldmatrix)
#define AS_OFF 0
#define BS_OFF (128 * ASTR)
#define GSMEM_BYTES (2 * 128 * ASTR * 2)   // 69632

__device__ __forceinline__ void ldsm_x4(uint32_t& r0, uint32_t& r1,
                                        uint32_t& r2, uint32_t& r3, uint32_t a) {
    asm volatile("ldmatrix.sync.aligned.m8n8.x4.shared.b16 {%0,%1,%2,%3}, [%4];"
                 : "=r"(r0), "=r"(r1), "=r"(r2), "=r"(r3) : "r"(a));
}

__device__ __forceinline__ void mma_fp16(float* d, const uint32_t* a,
                                         const uint32_t* b) {
    asm volatile(
        "mma.sync.aligned.m16n8k16.row.col.f32.f16.f16.f32 "
        "{%0,%1,%2,%3}, {%4,%5,%6,%7}, {%8,%9}, {%0,%1,%2,%3};"
        : "+f"(d[0]), "+f"(d[1]), "+f"(d[2]), "+f"(d[3])
        : "r"(a[0]), "r"(a[1]), "r"(a[2]), "r"(a[3]), "r"(b[0]), "r"(b[1]));
}

__global__ void __launch_bounds__(512)
k_gemm_mma(int layer) {
    extern __shared__ __half sm[];
    int tid = threadIdx.x;
    int wid = tid >> 5, lane = tid & 31;
    int row0 = blockIdx.x * 128;
    const __half* w16 = g_w16 + layer * DD * DD;

    // ---- fill A: 2048 uint4 tasks (r = t>>4, oct q = t&15) ----
    for (int t = tid; t < 2048; t += 512) {
        int q = t & 15, r = t >> 4;
        int grow = row0 + r;
        uint4 v = make_uint4(0, 0, 0, 0);
        if (grow < NN) v = *(const uint4*)&g_act[(size_t)grow * DD + q * 8];
        *(uint4*)&sm[AS_OFF + r * ASTR + q * 8] = v;
    }
    // ---- fill B ----
    for (int t = tid; t < 2048; t += 512) {
        int q = t & 15, n = t >> 4;
        uint4 v = *(const uint4*)&w16[n * DD + q * 8];
        *(uint4*)&sm[BS_OFF + n * ASTR + q * 8] = v;
    }
    __syncthreads();

    int wm = (wid >> 2) * 32;   // warp row origin within CTA tile
    int wn = (wid & 3) * 32;    // warp col origin

    float d[2][4][4];
    #pragma unroll
    for (int i = 0; i < 2; i++)
        #pragma unroll
        for (int j = 0; j < 4; j++)
            #pragma unroll
            for (int r = 0; r < 4; r++) d[i][j][r] = 0.f;

    uint32_t sbase = smem_u32(sm);

    #pragma unroll
    for (int kc = 0; kc < 8; kc++) {
        int k0 = kc * 16;
        uint32_t ah[2][4], bh[4][2];
        #pragma unroll
        for (int i = 0; i < 2; i++) {
            int r = wm + 16 * i + (lane & 15);
            int c = k0 + (lane >> 4) * 8;
            uint32_t ad = sbase + (uint32_t)(AS_OFF + r * ASTR + c) * 2;
            ldsm_x4(ah[i][0], ah[i][1], ah[i][2], ah[i][3], ad);
        }
        #pragma unroll
        for (int jj = 0; jj < 2; jj++) {
            int n = wn + 16 * jj + (lane & 15);
            int c = k0 + (lane >> 4) * 8;
            uint32_t r0, r1, r2, r3;
            uint32_t ad = sbase + (uint32_t)(BS_OFF + n * ASTR + c) * 2;
            ldsm_x4(r0, r1, r2, r3, ad);
            bh[2 * jj][0] = r0; bh[2 * jj + 1][0] = r1;
            bh[2 * jj][1] = r2; bh[2 * jj + 1][1] = r3;
        }
        #pragma unroll
        for (int i = 0; i < 2; i++)
            #pragma unroll
            for (int j = 0; j < 4; j++)
                mma_fp16(d[i][j], ah[i], bh[j]);
    }

    // ---- epilogue: scale by dinv[row], fp32 -> fp16 g_h ----
    int rr = lane >> 2;
    int cc = 2 * (lane & 3);
    #pragma unroll
    for (int i = 0; i < 2; i++) {
        int r_lo = row0 + wm + 16 * i + rr;
        int r_hi = r_lo + 8;
        float di_lo = (r_lo < NN) ? g_dinv[r_lo] : 0.f;
        float di_hi = (r_hi < NN) ? g_dinv[r_hi] : 0.f;
        #pragma unroll
        for (int j = 0; j < 4; j++) {
            int col = wn + 8 * j + cc;
            if (r_lo < NN) {
                __half2 h = __floats2half2_rn(d[i][j][0] * di_lo, d[i][j][1] * di_lo);
                *(__half2*)&g_h[(size_t)r_lo * DD + col] = h;
            }
            if (r_hi < NN) {
                __half2 h = __floats2half2_rn(d[i][j][2] * di_hi, d[i][j][3] * di_hi);
                *(__half2*)&g_h[(size_t)r_hi * DD + col] = h;
            }
        }
    }
}

// ------- aggregation: act[d] = relu(dinv[d]*(sum_src h'[s] + h'[d]) + b) -------
// 2 nodes per warp: each 16-lane half gathers full 256B rows with uint4 loads.
// NN = 50000 = 16 * 3125, so every block's 16 nodes are valid.
__device__ __forceinline__ void add8(float* a, uint4 v) {
    __half2* p = (__half2*)&v;
    #pragma unroll
    for (int k = 0; k < 4; k++) {
        float2 f = __half22float2(p[k]);
        a[2 * k] += f.x;
        a[2 * k + 1] += f.y;
    }
}

__global__ void __launch_bounds__(256) k_aggregate(const float* __restrict__ bias) {
    int wid = threadIdx.x >> 5, lane = threadIdx.x & 31;
    int half = lane >> 4, hl = lane & 15;
    int node = blockIdx.x * 16 + wid * 2 + half;
    const uint4* h4 = (const uint4*)g_h;

    float a[8];
    {   // self term h'[d]
        uint4 v = h4[(size_t)node * 16 + hl];
        __half2* p = (__half2*)&v;
        #pragma unroll
        for (int k = 0; k < 4; k++) {
            float2 f = __half22float2(p[k]);
            a[2 * k] = f.x;
            a[2 * k + 1] = f.y;
        }
    }

    int s = g_rowptr[node], e = g_rowptr[node + 1];
    int chunks = (e - s + 15) >> 4;
    int cmax = max(chunks, __shfl_xor_sync(0xffffffffu, chunks, 16));

    for (int t = 0; t < cmax; t++) {
        int p = s + t * 16 + hl;
        int idx = (t < chunks && p < e) ? g_csrc[p] : -1;
        #pragma unroll
        for (int u = 0; u < 16; u++) {
            int uu = __shfl_sync(0xffffffffu, idx, (half << 4) + u);
            if (uu >= 0) add8(a, h4[(size_t)uu * 16 + hl]);
        }
    }

    float di = g_dinv[node];
    const float4* b4 = (const float4*)bias;
    float4 b0 = b4[hl * 2], b1 = b4[hl * 2 + 1];
    float r0 = fmaxf(fmaf(a[0], di, b0.x), 0.f);
    float r1 = fmaxf(fmaf(a[1], di, b0.y), 0.f);
    float r2 = fmaxf(fmaf(a[2], di, b0.z), 0.f);
    float r3 = fmaxf(fmaf(a[3], di, b0.w), 0.f);
    float r4 = fmaxf(fmaf(a[4], di, b1.x), 0.f);
    float r5 = fmaxf(fmaf(a[5], di, b1.y), 0.f);
    float r6 = fmaxf(fmaf(a[6], di, b1.z), 0.f);
    float r7 = fmaxf(fmaf(a[7], di, b1.w), 0.f);

    __half2 p0 = __floats2half2_rn(r0, r1);
    __half2 p1 = __floats2half2_rn(r2, r3);
    __half2 p2 = __floats2half2_rn(r4, r5);
    __half2 p3 = __floats2half2_rn(r6, r7);
    ((uint4*)g_act)[(size_t)node * 16 + hl] =
        make_uint4(*(uint32_t*)&p0, *(uint32_t*)&p1,
                   *(uint32_t*)&p2, *(uint32_t*)&p3);
}

// ---------------- pool (mean per graph) + classifier ----------------
__global__ void __launch_bounds__(128) k_pool_cls(const float* __restrict__ Wc,
                                                  const float* __restrict__ bc,
                                                  const float* __restrict__ Wo,
                                                  const float* __restrict__ bo,
                                                  float* __restrict__ out) {
    __shared__ float pooled[DD];
    __shared__ float zs[HH];
    int g = blockIdx.x, c = threadIdx.x;
    int s = g_gptr[g], e = g_gptr[g + 1];
    float acc = 0.f;
    for (int i = s; i < e; i++)
        acc += __half2float(g_act[(size_t)i * DD + c]);
    pooled[c] = acc / fmaxf((float)(e - s), 1.0f);
    __syncthreads();
    if (c < HH) {
        float z = bc[c];
        #pragma unroll
        for (int dd = 0; dd < DD; dd++) z = fmaf(pooled[dd], Wc[dd * HH + c], z);
        z = fmaxf(z, 0.f);
        zs[c] = z * Wo[c];
    }
    __syncthreads();
    if (c == 0) {
        float r = bo[0];
        #pragma unroll
        for (int h = 0; h < HH; h++) r += zs[h];
        out[g] = r;
    }
}

// ---------------- launch ----------------
extern "C" void kernel_launch(void* const* d_in, const int* in_sizes, int n_in,
                              void* d_out, int out_size) {
    const float* x  = (const float*)d_in[0];
    const int*   ei = (const int*)d_in[1];      // [2, E] int32
    const int*   batch = (const int*)d_in[2];
    const float* W1 = (const float*)d_in[3];
    const float* b1 = (const float*)d_in[4];
    const float* W2 = (const float*)d_in[5];
    const float* b2 = (const float*)d_in[6];
    const float* W3 = (const float*)d_in[7];
    const float* b3 = (const float*)d_in[8];
    const float* Wc = (const float*)d_in[9];
    const float* bc = (const float*)d_in[10];
    const float* Wo = (const float*)d_in[11];
    const float* bo = (const float*)d_in[12];
    float* out = (float*)d_out;

    const int* src = ei;
    const int* dst = ei + EE;

    cudaFuncSetAttribute(k_gemm_mma, cudaFuncAttributeMaxDynamicSharedMemorySize,
                         GSMEM_BYTES);

    const int NB_N = (NN + 255) / 256;
    const int NB_E = (EE + 255) / 256;

    // graph structure (once per call)
    k_init_nodes<<<NB_N, 256>>>();
    k_hist<<<NB_E, 256>>>(dst);
    k_scan1<<<NB_SCAN, 1024>>>();
    k_scan3_gptr<<<NB_SCAN, 1024>>>(batch);
    k_fill<<<NB_E, 256>>>(src, dst);

    // operand conversion (x + all W), one kernel
    k_convert<<<XBLK + WBLK, 256>>>(x, W1, W2, W3);

    const int NB_G = (NN + 127) / 128;    // gemm blocks
    const int NB_A = NN / 16;             // aggregate blocks (exact)

    // layer 1
    k_gemm_mma<<<NB_G, 512, GSMEM_BYTES>>>(0);
    k_aggregate<<<NB_A, 256>>>(b1);
    // layer 2
    k_gemm_mma<<<NB_G, 512, GSMEM_BYTES>>>(1);
    k_aggregate<<<NB_A, 256>>>(b2);
    // layer 3
    k_gemm_mma<<<NB_G, 512, GSMEM_BYTES>>>(2);
    k_aggregate<<<NB_A, 256>>>(b3);

    // pool + classifier
    k_pool_cls<<<GG, 128>>>(Wc, bc, Wo, bo, out);
}